// round 10
// baseline (speedup 1.0000x reference)
#include <cuda_runtime.h>
#include <cuda_bf16.h>
#include <cstdint>

#define NN   50000
#define EE   800000
#define HIDC 256
#define OUTC 128
#define NB_S 98   // ceil(NN/512)

// ---------------- scratch (static device globals; no allocation) ----------------
__device__ int   d_is64;
__device__ int   d_deg[NN];
__device__ float d_dinv[NN];
__device__ int   d_rowptr[NN + 1];
__device__ int   d_cursor[NN];
__device__ int   d_bsum[NB_S];
__device__ int   d_boff[NB_S];
__device__ int2  d_csr[EE];                    // (src, w as float bits)
__device__ float d_h0[(size_t)NN * HIDC];      // x @ W1; later reused as GEMM1 K-partial acc
__device__ float d_h [(size_t)NN * HIDC];      // relu(Agg(h0) + b1)
__device__ __nv_bfloat16 d_ghi[(size_t)NN * HIDC];  // split of Agg(h)
__device__ __nv_bfloat16 d_glo[(size_t)NN * HIDC];
__device__ __nv_bfloat16 d_W1Thi[HIDC * HIDC];  // W1^T  [n][k]
__device__ __nv_bfloat16 d_W1Tlo[HIDC * HIDC];
__device__ __nv_bfloat16 d_BcThi[HIDC * HIDC];  // [Wmu|Wls]^T  [n][k]
__device__ __nv_bfloat16 d_BcTlo[HIDC * HIDC];
__device__ float d_bcat[256];                   // [b_mu | b_ls]

// ---------------- helpers ----------------
__device__ __forceinline__ uint32_t smem_u32(const void* p) {
    uint32_t a;
    asm("{ .reg .u64 t; cvta.to.shared.u64 t, %1; cvt.u32.u64 %0, t; }" : "=r"(a) : "l"(p));
    return a;
}
__device__ __forceinline__ void bsplit(float v, __nv_bfloat16& h, __nv_bfloat16& l) {
    h = __float2bfloat16(v);
    l = __float2bfloat16(v - __bfloat162float(h));
}
__device__ __forceinline__ void split2(float a, float b, uint32_t& h, uint32_t& l) {
    __nv_bfloat16 ha, la, hb, lb;
    bsplit(a, ha, la);
    bsplit(b, hb, lb);
    h = (uint32_t)__bfloat16_as_ushort(ha) | ((uint32_t)__bfloat16_as_ushort(hb) << 16);
    l = (uint32_t)__bfloat16_as_ushort(la) | ((uint32_t)__bfloat16_as_ushort(lb) << 16);
}
__device__ __forceinline__ void ldmat_x4(uint32_t& r0, uint32_t& r1, uint32_t& r2,
                                         uint32_t& r3, uint32_t addr) {
    asm volatile("ldmatrix.sync.aligned.m8n8.x4.shared.b16 {%0,%1,%2,%3}, [%4];"
                 : "=r"(r0), "=r"(r1), "=r"(r2), "=r"(r3) : "r"(addr));
}
__device__ __forceinline__ void mma_bf16(float* c, const uint32_t* a,
                                         uint32_t b0, uint32_t b1) {
    asm volatile("mma.sync.aligned.m16n8k16.row.col.f32.bf16.bf16.f32 "
                 "{%0,%1,%2,%3}, {%4,%5,%6,%7}, {%8,%9}, {%0,%1,%2,%3};"
                 : "+f"(c[0]), "+f"(c[1]), "+f"(c[2]), "+f"(c[3])
                 : "r"(a[0]), "r"(a[1]), "r"(a[2]), "r"(a[3]), "r"(b0), "r"(b1));
}
__device__ __forceinline__ uint32_t sw_addr(uint32_t base, int row, int kc) {
    return base + row * 128 + ((kc ^ (row & 7)) << 4);
}
__device__ __forceinline__ int load_idx(const void* ei, size_t pos) {
    if (d_is64) return (int)((const long long*)ei)[pos];
    return ((const int*)ei)[pos];
}

// ---------------- setup kernels ----------------
__global__ void k_zero(const unsigned long long* __restrict__ ei) {
    int i = blockIdx.x * 256 + threadIdx.x;
    if (i < NN) d_deg[i] = 0;
    if (i == 0) {
        int is64 = 1;
        for (int j = 0; j < 128; j++)
            if (ei[j] >= (1ull << 32)) { is64 = 0; break; }
        d_is64 = is64;
    }
}
__global__ void k_count(const void* __restrict__ ei) {
    int e = blockIdx.x * 256 + threadIdx.x;
    if (e < EE) atomicAdd(&d_deg[load_idx(ei, (size_t)EE + e)], 1);
}
// ---- 3-phase parallel scan (edge-only counts; self-loop via +1 in dinv)
__global__ __launch_bounds__(512) void k_scan1() {
    __shared__ int sw[16];
    int b = blockIdx.x, tid = threadIdx.x;
    int i = b * 512 + tid;
    int lane = tid & 31, wid = tid >> 5;
    int deg = (i < NN) ? d_deg[i] : 0;
    if (i < NN) d_dinv[i] = rsqrtf((float)(deg + 1));
    int x = deg;
#pragma unroll
    for (int d = 1; d < 32; d <<= 1) {
        int t = __shfl_up_sync(0xffffffffu, x, d);
        if (lane >= d) x += t;
    }
    if (lane == 31) sw[wid] = x;
    __syncthreads();
    if (wid == 0 && lane < 16) {
        int y = sw[lane];
#pragma unroll
        for (int d = 1; d < 16; d <<= 1) {
            int t = __shfl_up_sync(0xffffu, y, d);
            if (lane >= d) y += t;
        }
        sw[lane] = y;
    }
    __syncthreads();
    int incl = x + ((wid > 0) ? sw[wid - 1] : 0);
    if (i < NN) d_rowptr[i + 1] = incl;
    if (tid == 511) d_bsum[b] = incl;
}
__global__ __launch_bounds__(128) void k_scan2() {
    __shared__ int sw[4];
    int tid = threadIdx.x, lane = tid & 31, wid = tid >> 5;
    int v = (tid < NB_S) ? d_bsum[tid] : 0;
    int x = v;
#pragma unroll
    for (int d = 1; d < 32; d <<= 1) {
        int t = __shfl_up_sync(0xffffffffu, x, d);
        if (lane >= d) x += t;
    }
    if (lane == 31) sw[wid] = x;
    __syncthreads();
    if (wid == 0 && lane < 4) {
        int y = sw[lane];
#pragma unroll
        for (int d = 1; d < 4; d <<= 1) {
            int t = __shfl_up_sync(0xfu, y, d);
            if (lane >= d) y += t;
        }
        sw[lane] = y;
    }
    __syncthreads();
    int incl = x + ((wid > 0) ? sw[wid - 1] : 0);
    if (tid < NB_S) d_boff[tid] = incl - v;  // exclusive
}
__global__ __launch_bounds__(512) void k_scan3() {
    int i = blockIdx.x * 512 + threadIdx.x;
    if (i < NN) {
        int r = d_rowptr[i + 1] + d_boff[i >> 9];
        d_rowptr[i + 1] = r;
        d_cursor[i]     = r - d_deg[i];
    }
    if (i == 0) d_rowptr[0] = 0;
}
__global__ void k_fill(const void* __restrict__ ei) {
    int e = blockIdx.x * 256 + threadIdx.x;
    if (e < EE) {
        int s = load_idx(ei, (size_t)e);
        int d = load_idx(ei, (size_t)EE + e);
        int pos = atomicAdd(&d_cursor[d], 1);
        d_csr[pos] = make_int2(s, __float_as_int(d_dinv[s] * d_dinv[d]));
    }
}

// pack + transpose + bf16-split the weights
__global__ void k_pack2(const float* __restrict__ W1,
                        const float* __restrict__ Wmu, const float* __restrict__ Wls,
                        const float* __restrict__ bmu, const float* __restrict__ bls) {
    int idx = blockIdx.x * 256 + threadIdx.x;
    if (idx < 65536) {
        int n = idx >> 8, k = idx & 255;
        bsplit(W1[k * 256 + n], d_W1Thi[idx], d_W1Tlo[idx]);
        float bc = (n < OUTC) ? Wmu[k * OUTC + n] : Wls[k * OUTC + (n - OUTC)];
        bsplit(bc, d_BcThi[idx], d_BcTlo[idx]);
    }
    if (idx < 256) d_bcat[idx] = (idx < OUTC) ? bmu[idx] : bls[idx - OUTC];
}

// ---------------- aggregation (gather via CSR, feature-half per launch) -------
// BUF=0: d_h0 -> d_h (relu+bias). BUF=1: d_h -> (d_ghi, d_glo).
// block (32,8): 8 nodes, 32 lanes x float4 = 128 features starting at c4off*4.
template <int BUF>
__global__ __launch_bounds__(256) void k_agg(const float* __restrict__ bias, int c4off) {
    int node = blockIdx.x * 8 + threadIdx.y;
    if (node >= NN) return;
    int f = threadIdx.x + c4off;  // float4 index within the 64-wide row
    const float4* sf = (BUF == 0) ? (const float4*)d_h0 : (const float4*)d_h;

    float di = d_dinv[node];
    float w0 = di * di;
    float4 acc = sf[(size_t)node * 64 + f];
    acc.x *= w0; acc.y *= w0; acc.z *= w0; acc.w *= w0;

    int beg = d_rowptr[node], end = d_rowptr[node + 1];
    int e = beg;
    for (; e + 4 <= end; e += 4) {
        int2 c0 = d_csr[e];
        int2 c1 = d_csr[e + 1];
        int2 c2 = d_csr[e + 2];
        int2 c3 = d_csr[e + 3];
        float4 v0 = sf[(size_t)c0.x * 64 + f];
        float4 v1 = sf[(size_t)c1.x * 64 + f];
        float4 v2 = sf[(size_t)c2.x * 64 + f];
        float4 v3 = sf[(size_t)c3.x * 64 + f];
        float w0f = __int_as_float(c0.y), w1f = __int_as_float(c1.y);
        float w2f = __int_as_float(c2.y), w3f = __int_as_float(c3.y);
        acc.x += w0f * v0.x + w1f * v1.x + w2f * v2.x + w3f * v3.x;
        acc.y += w0f * v0.y + w1f * v1.y + w2f * v2.y + w3f * v3.y;
        acc.z += w0f * v0.z + w1f * v1.z + w2f * v2.z + w3f * v3.z;
        acc.w += w0f * v0.w + w1f * v1.w + w2f * v2.w + w3f * v3.w;
    }
    for (; e < end; e++) {
        int2 c = d_csr[e];
        float w = __int_as_float(c.y);
        float4 v = sf[(size_t)c.x * 64 + f];
        acc.x += w * v.x;
        acc.y += w * v.y;
        acc.z += w * v.z;
        acc.w += w * v.w;
    }
    if (BUF == 0) {
        float4 b = ((const float4*)bias)[f];
        acc.x = fmaxf(acc.x + b.x, 0.f);
        acc.y = fmaxf(acc.y + b.y, 0.f);
        acc.z = fmaxf(acc.z + b.z, 0.f);
        acc.w = fmaxf(acc.w + b.w, 0.f);
        ((float4*)d_h)[(size_t)node * 64 + f] = acc;
    } else {
        uint2 hv, lv;
        split2(acc.x, acc.y, hv.x, lv.x);
        split2(acc.z, acc.w, hv.y, lv.y);
        *(uint2*)&d_ghi[(size_t)node * 256 + f * 4] = hv;
        *(uint2*)&d_glo[(size_t)node * 256 + f * 4] = lv;
    }
}

// ---------------- mma.sync bf16-split GEMM ----------------
// MODE 0: h0 = x @ W1^T (full K, bn half selected by bn0; grid.x=1).
// MODE 1, KH=0: partial = g @ Bc^T over K[0:128) -> raw fp32 into d_h0 (grid.x=2).
// MODE 1, KH=1: += over K[128:256), add d_h0 partial + bias, split-store to out.
#define TILE_B 16384
#define GSMEM  (4 * TILE_B)

__device__ __forceinline__ void load_tile64(char* tile, const __nv_bfloat16* __restrict__ src,
                                            int row0, int nvalid, int col0) {
    int t = threadIdx.x;
    int r = t >> 1;
    int hb = (t & 1) * 64;
    const char* srow = (const char*)(src + (size_t)(row0 + r) * 256 + col0);
    bool valid = r < nvalid;
#pragma unroll
    for (int i = 0; i < 4; i++) {
        int b = hb + i * 16;
        uint4 v = valid ? *(const uint4*)(srow + b) : make_uint4(0u, 0u, 0u, 0u);
        uint32_t off = (uint32_t)(r * 128 + b);
        off ^= ((off >> 3) & 0x70);
        *(uint4*)(tile + off) = v;
    }
}

__device__ __forceinline__ void load_tile64_split(char* tilehi, char* tilelo,
                                                  const float* __restrict__ src,
                                                  int row0, int nvalid, int col0) {
    int t = threadIdx.x;
    int r = t >> 1;
    int hf = (t & 1) * 32;
    const float* srow = src + (size_t)(row0 + r) * 256 + col0 + hf;
    bool valid = r < nvalid;
#pragma unroll
    for (int i = 0; i < 4; i++) {
        float4 f0 = valid ? *(const float4*)(srow + i * 8)     : make_float4(0.f, 0.f, 0.f, 0.f);
        float4 f1 = valid ? *(const float4*)(srow + i * 8 + 4) : make_float4(0.f, 0.f, 0.f, 0.f);
        uint4 hv, lv;
        split2(f0.x, f0.y, hv.x, lv.x);
        split2(f0.z, f0.w, hv.y, lv.y);
        split2(f1.x, f1.y, hv.z, lv.z);
        split2(f1.z, f1.w, hv.w, lv.w);
        uint32_t off = (uint32_t)(r * 128 + hf * 2 + i * 16);
        off ^= ((off >> 3) & 0x70);
        *(uint4*)(tilehi + off) = hv;
        *(uint4*)(tilelo + off) = lv;
    }
}

template <int MODE, int KH>
__global__ __launch_bounds__(256) void k_gemm_mma(const float* __restrict__ Ax,
                                                  float* __restrict__ Cp, int bn0) {
    extern __shared__ char smem[];
    char* sAhi = smem;
    char* sAlo = smem + TILE_B;
    char* sBhi = smem + 2 * TILE_B;
    char* sBlo = smem + 3 * TILE_B;
    uint32_t bAhi = smem_u32(sAhi), bAlo = bAhi + TILE_B;
    uint32_t bBhi = bAhi + 2 * TILE_B, bBlo = bAhi + 3 * TILE_B;

    int tid = threadIdx.x, wid = tid >> 5, lane = tid & 31;
    int wm = wid >> 1, wn = wid & 1;
    int bn = blockIdx.x * 128 + bn0;
    int bm = blockIdx.y * 128;

    const __nv_bfloat16* Bhi = (MODE == 0) ? d_W1Thi : d_BcThi;
    const __nv_bfloat16* Blo = (MODE == 0) ? d_W1Tlo : d_BcTlo;

    int navalid = NN - bm; if (navalid > 128) navalid = 128;

    float acc[2][8][4];
#pragma unroll
    for (int i = 0; i < 2; i++)
#pragma unroll
        for (int j = 0; j < 8; j++)
#pragma unroll
            for (int q = 0; q < 4; q++) acc[i][j][q] = 0.f;

    int a_row_off = ((lane >> 3) & 1) * 8 + (lane & 7);
    int a_kc_off  = (lane >> 4);
    int b_row_off = (lane >> 4) * 8 + (lane & 7);
    int b_kc_off  = ((lane >> 3) & 1);

    const int C0 = (MODE == 0) ? 0 : KH * 2;
    const int C1 = (MODE == 0) ? 4 : KH * 2 + 2;

    for (int c = C0; c < C1; c++) {
        if (c > C0) __syncthreads();
        if (MODE == 0) {
            load_tile64_split(sAhi, sAlo, Ax, bm, navalid, c * 64);
        } else {
            load_tile64(sAhi, d_ghi, bm, navalid, c * 64);
            load_tile64(sAlo, d_glo, bm, navalid, c * 64);
        }
        load_tile64(sBhi, Bhi, bn, 128, c * 64);
        load_tile64(sBlo, Blo, bn, 128, c * 64);
        __syncthreads();

#pragma unroll
        for (int ks = 0; ks < 4; ks++) {
            int kc0 = ks * 2;
            uint32_t ahi[2][4], alo[2][4];
#pragma unroll
            for (int mi = 0; mi < 2; mi++) {
                int row = wm * 32 + mi * 16 + a_row_off;
                int kc  = kc0 + a_kc_off;
                ldmat_x4(ahi[mi][0], ahi[mi][1], ahi[mi][2], ahi[mi][3],
                         sw_addr(bAhi, row, kc));
                ldmat_x4(alo[mi][0], alo[mi][1], alo[mi][2], alo[mi][3],
                         sw_addr(bAlo, row, kc));
            }
#pragma unroll
            for (int ng = 0; ng < 4; ng++) {
                int nrow = wn * 64 + ng * 16 + b_row_off;
                int kc   = kc0 + b_kc_off;
                uint32_t bh[4], bl[4];
                ldmat_x4(bh[0], bh[1], bh[2], bh[3], sw_addr(bBhi, nrow, kc));
                ldmat_x4(bl[0], bl[1], bl[2], bl[3], sw_addr(bBlo, nrow, kc));
#pragma unroll
                for (int mi = 0; mi < 2; mi++) {
                    mma_bf16(acc[mi][ng * 2],     ahi[mi], bh[0], bh[1]);
                    mma_bf16(acc[mi][ng * 2],     ahi[mi], bl[0], bl[1]);
                    mma_bf16(acc[mi][ng * 2],     alo[mi], bh[0], bh[1]);
                    mma_bf16(acc[mi][ng * 2 + 1], ahi[mi], bh[2], bh[3]);
                    mma_bf16(acc[mi][ng * 2 + 1], ahi[mi], bl[2], bl[3]);
                    mma_bf16(acc[mi][ng * 2 + 1], alo[mi], bh[2], bh[3]);
                }
            }
        }
    }

#pragma unroll
    for (int mi = 0; mi < 2; mi++) {
        int r0 = bm + wm * 32 + mi * 16 + (lane >> 2);
#pragma unroll
        for (int ni = 0; ni < 8; ni++) {
            int col = wn * 64 + ni * 8 + (lane & 3) * 2;
            float* a = acc[mi][ni];
            if (MODE == 0 || KH == 0) {
                // raw store: MODE0 -> h0; MODE1/KH0 -> K-partial into d_h0
                if (r0 < NN)
                    *(float2*)&d_h0[(size_t)r0 * 256 + bn + col] = make_float2(a[0], a[1]);
                if (r0 + 8 < NN)
                    *(float2*)&d_h0[(size_t)(r0 + 8) * 256 + bn + col] = make_float2(a[2], a[3]);
            } else {
                float bx = d_bcat[bn + col], by = d_bcat[bn + col + 1];
                size_t half = (bn < OUTC) ? 0 : (size_t)NN * OUTC;
                int ocol = (bn < OUTC) ? (bn + col) : (bn - OUTC + col);
                if (r0 < NN) {
                    float2 p = *(float2*)&d_h0[(size_t)r0 * 256 + bn + col];
                    *(float2*)&Cp[half + (size_t)r0 * OUTC + ocol] =
                        make_float2(a[0] + p.x + bx, a[1] + p.y + by);
                }
                if (r0 + 8 < NN) {
                    float2 p = *(float2*)&d_h0[(size_t)(r0 + 8) * 256 + bn + col];
                    *(float2*)&Cp[half + (size_t)(r0 + 8) * OUTC + ocol] =
                        make_float2(a[2] + p.x + bx, a[3] + p.y + by);
                }
            }
        }
    }
}

// ---------------- launch ----------------
extern "C" void kernel_launch(void* const* d_in, const int* in_sizes, int n_in,
                              void* d_out, int out_size) {
    const float* x   = (const float*)d_in[0];
    const void*  ei  = d_in[1];
    const float* W1  = (const float*)d_in[2];
    const float* b1  = (const float*)d_in[3];
    const float* Wmu = (const float*)d_in[4];
    const float* bmu = (const float*)d_in[5];
    const float* Wls = (const float*)d_in[6];
    const float* bls = (const float*)d_in[7];
    float* out = (float*)d_out;

    cudaFuncSetAttribute(k_gemm_mma<0, 0>, cudaFuncAttributeMaxDynamicSharedMemorySize, GSMEM);
    cudaFuncSetAttribute(k_gemm_mma<1, 0>, cudaFuncAttributeMaxDynamicSharedMemorySize, GSMEM);
    cudaFuncSetAttribute(k_gemm_mma<1, 1>, cudaFuncAttributeMaxDynamicSharedMemorySize, GSMEM);

    dim3 g1(1, (NN + 127) / 128);   // GEMM0 halves
    dim3 g2(2, (NN + 127) / 128);   // GEMM1 (full N per K-half)
    dim3 agrid((NN + 7) / 8);
    dim3 ablk(32, 8);

    cudaStream_t s1;
    cudaStreamCreateWithFlags(&s1, cudaStreamNonBlocking);
    cudaEvent_t e0, eG0a, eG0b, eA1a, eG1a;
    cudaEventCreateWithFlags(&e0,   cudaEventDisableTiming);
    cudaEventCreateWithFlags(&eG0a, cudaEventDisableTiming);
    cudaEventCreateWithFlags(&eG0b, cudaEventDisableTiming);
    cudaEventCreateWithFlags(&eA1a, cudaEventDisableTiming);
    cudaEventCreateWithFlags(&eG1a, cudaEventDisableTiming);

    cudaEventRecord(e0, 0);
    cudaStreamWaitEvent(s1, e0, 0);

    // branch B (s1): pack weights, GEMM0 in two N-halves
    k_pack2<<<(65536 + 255) / 256, 256, 0, s1>>>(W1, Wmu, Wls, bmu, bls);
    k_gemm_mma<0, 0><<<g1, 256, GSMEM, s1>>>(x, nullptr, 0);
    cudaEventRecord(eG0a, s1);
    k_gemm_mma<0, 0><<<g1, 256, GSMEM, s1>>>(x, nullptr, 128);
    cudaEventRecord(eG0b, s1);

    // branch A (stream 0): CSR build
    k_zero<<<(NN + 255) / 256, 256>>>((const unsigned long long*)ei);
    k_count<<<(EE + 255) / 256, 256>>>(ei);
    k_scan1<<<NB_S, 512>>>();
    k_scan2<<<1, 128>>>();
    k_scan3<<<NB_S, 512>>>();
    k_fill<<<(EE + 255) / 256, 256>>>(ei);

    // agg0a (features 0:128) after GEMM0a; overlaps GEMM0b
    cudaStreamWaitEvent(0, eG0a, 0);
    k_agg<0><<<agrid, ablk>>>(b1, 0);
    cudaStreamWaitEvent(0, eG0b, 0);
    k_agg<0><<<agrid, ablk>>>(b1, 32);

    // agg1a (features 0:128) -> GEMM1 K-half 0 on s1, overlapping agg1b
    k_agg<1><<<agrid, ablk>>>(nullptr, 0);
    cudaEventRecord(eA1a, 0);
    cudaStreamWaitEvent(s1, eA1a, 0);
    k_gemm_mma<1, 0><<<g2, 256, GSMEM, s1>>>(nullptr, out, 0);
    cudaEventRecord(eG1a, s1);

    k_agg<1><<<agrid, ablk>>>(nullptr, 32);
    cudaStreamWaitEvent(0, eG1a, 0);
    k_gemm_mma<1, 1><<<g2, 256, GSMEM>>>(nullptr, out, 0);
}

// round 12
// speedup vs baseline: 1.1369x; 1.1369x over previous
#include <cuda_runtime.h>
#include <cuda_bf16.h>
#include <cstdint>

#define NN   50000
#define EE   800000
#define HIDC 256
#define OUTC 128
#define NB_S 98   // ceil(NN/512)
#define MSPLIT 25088   // 196 * 128, node/row split point for agg1/GEMM1 overlap

// ---------------- scratch (static device globals; no allocation) ----------------
__device__ int   d_is64;
__device__ int   d_deg[NN];
__device__ float d_dinv[NN];
__device__ int   d_rowptr[NN + 1];
__device__ int   d_cursor[NN];
__device__ int   d_bsum[NB_S];
__device__ int   d_boff[NB_S];
__device__ int2  d_csr[EE];                    // (src, w as float bits)
__device__ float d_h0[(size_t)NN * HIDC];      // x @ W1
__device__ float d_h [(size_t)NN * HIDC];      // relu(Agg(h0) + b1)
__device__ __nv_bfloat16 d_ghi[(size_t)NN * HIDC];  // split of Agg(h)
__device__ __nv_bfloat16 d_glo[(size_t)NN * HIDC];
__device__ __nv_bfloat16 d_W1Thi[HIDC * HIDC];  // W1^T  [n][k]
__device__ __nv_bfloat16 d_W1Tlo[HIDC * HIDC];
__device__ __nv_bfloat16 d_BcThi[HIDC * HIDC];  // [Wmu|Wls]^T  [n][k]
__device__ __nv_bfloat16 d_BcTlo[HIDC * HIDC];
__device__ float d_bcat[256];                   // [b_mu | b_ls]

// ---------------- helpers ----------------
__device__ __forceinline__ uint32_t smem_u32(const void* p) {
    uint32_t a;
    asm("{ .reg .u64 t; cvta.to.shared.u64 t, %1; cvt.u32.u64 %0, t; }" : "=r"(a) : "l"(p));
    return a;
}
__device__ __forceinline__ void bsplit(float v, __nv_bfloat16& h, __nv_bfloat16& l) {
    h = __float2bfloat16(v);
    l = __float2bfloat16(v - __bfloat162float(h));
}
__device__ __forceinline__ void split2(float a, float b, uint32_t& h, uint32_t& l) {
    __nv_bfloat16 ha, la, hb, lb;
    bsplit(a, ha, la);
    bsplit(b, hb, lb);
    h = (uint32_t)__bfloat16_as_ushort(ha) | ((uint32_t)__bfloat16_as_ushort(hb) << 16);
    l = (uint32_t)__bfloat16_as_ushort(la) | ((uint32_t)__bfloat16_as_ushort(lb) << 16);
}
__device__ __forceinline__ void ldmat_x4(uint32_t& r0, uint32_t& r1, uint32_t& r2,
                                         uint32_t& r3, uint32_t addr) {
    asm volatile("ldmatrix.sync.aligned.m8n8.x4.shared.b16 {%0,%1,%2,%3}, [%4];"
                 : "=r"(r0), "=r"(r1), "=r"(r2), "=r"(r3) : "r"(addr));
}
__device__ __forceinline__ void mma_bf16(float* c, const uint32_t* a,
                                         uint32_t b0, uint32_t b1) {
    asm volatile("mma.sync.aligned.m16n8k16.row.col.f32.bf16.bf16.f32 "
                 "{%0,%1,%2,%3}, {%4,%5,%6,%7}, {%8,%9}, {%0,%1,%2,%3};"
                 : "+f"(c[0]), "+f"(c[1]), "+f"(c[2]), "+f"(c[3])
                 : "r"(a[0]), "r"(a[1]), "r"(a[2]), "r"(a[3]), "r"(b0), "r"(b1));
}
__device__ __forceinline__ uint32_t sw_addr(uint32_t base, int row, int kc) {
    return base + row * 128 + ((kc ^ (row & 7)) << 4);
}
__device__ __forceinline__ int load_idx(const void* ei, size_t pos) {
    if (d_is64) return (int)((const long long*)ei)[pos];
    return ((const int*)ei)[pos];
}

// ---------------- setup kernels ----------------
__global__ void k_zero(const unsigned long long* __restrict__ ei) {
    int i = blockIdx.x * 256 + threadIdx.x;
    if (i < NN) d_deg[i] = 0;
    if (i == 0) {
        int is64 = 1;
        for (int j = 0; j < 128; j++)
            if (ei[j] >= (1ull << 32)) { is64 = 0; break; }
        d_is64 = is64;
    }
}
__global__ void k_count(const void* __restrict__ ei) {
    int e = blockIdx.x * 256 + threadIdx.x;
    if (e < EE) atomicAdd(&d_deg[load_idx(ei, (size_t)EE + e)], 1);
}
// ---- 3-phase parallel scan (edge-only counts; self-loop via +1 in dinv)
__global__ __launch_bounds__(512) void k_scan1() {
    __shared__ int sw[16];
    int b = blockIdx.x, tid = threadIdx.x;
    int i = b * 512 + tid;
    int lane = tid & 31, wid = tid >> 5;
    int deg = (i < NN) ? d_deg[i] : 0;
    if (i < NN) d_dinv[i] = rsqrtf((float)(deg + 1));
    int x = deg;
#pragma unroll
    for (int d = 1; d < 32; d <<= 1) {
        int t = __shfl_up_sync(0xffffffffu, x, d);
        if (lane >= d) x += t;
    }
    if (lane == 31) sw[wid] = x;
    __syncthreads();
    if (wid == 0 && lane < 16) {
        int y = sw[lane];
#pragma unroll
        for (int d = 1; d < 16; d <<= 1) {
            int t = __shfl_up_sync(0xffffu, y, d);
            if (lane >= d) y += t;
        }
        sw[lane] = y;
    }
    __syncthreads();
    int incl = x + ((wid > 0) ? sw[wid - 1] : 0);
    if (i < NN) d_rowptr[i + 1] = incl;
    if (tid == 511) d_bsum[b] = incl;
}
__global__ __launch_bounds__(128) void k_scan2() {
    __shared__ int sw[4];
    int tid = threadIdx.x, lane = tid & 31, wid = tid >> 5;
    int v = (tid < NB_S) ? d_bsum[tid] : 0;
    int x = v;
#pragma unroll
    for (int d = 1; d < 32; d <<= 1) {
        int t = __shfl_up_sync(0xffffffffu, x, d);
        if (lane >= d) x += t;
    }
    if (lane == 31) sw[wid] = x;
    __syncthreads();
    if (wid == 0 && lane < 4) {
        int y = sw[lane];
#pragma unroll
        for (int d = 1; d < 4; d <<= 1) {
            int t = __shfl_up_sync(0xfu, y, d);
            if (lane >= d) y += t;
        }
        sw[lane] = y;
    }
    __syncthreads();
    int incl = x + ((wid > 0) ? sw[wid - 1] : 0);
    if (tid < NB_S) d_boff[tid] = incl - v;  // exclusive
}
__global__ __launch_bounds__(512) void k_scan3() {
    int i = blockIdx.x * 512 + threadIdx.x;
    if (i < NN) {
        int r = d_rowptr[i + 1] + d_boff[i >> 9];
        d_rowptr[i + 1] = r;
        d_cursor[i]     = r - d_deg[i];
    }
    if (i == 0) d_rowptr[0] = 0;
}
__global__ void k_fill(const void* __restrict__ ei) {
    int e = blockIdx.x * 256 + threadIdx.x;
    if (e < EE) {
        int s = load_idx(ei, (size_t)e);
        int d = load_idx(ei, (size_t)EE + e);
        int pos = atomicAdd(&d_cursor[d], 1);
        d_csr[pos] = make_int2(s, __float_as_int(d_dinv[s] * d_dinv[d]));
    }
}

// pack + transpose + bf16-split the weights
__global__ void k_pack2(const float* __restrict__ W1,
                        const float* __restrict__ Wmu, const float* __restrict__ Wls,
                        const float* __restrict__ bmu, const float* __restrict__ bls) {
    int idx = blockIdx.x * 256 + threadIdx.x;
    if (idx < 65536) {
        int n = idx >> 8, k = idx & 255;
        bsplit(W1[k * 256 + n], d_W1Thi[idx], d_W1Tlo[idx]);
        float bc = (n < OUTC) ? Wmu[k * OUTC + n] : Wls[k * OUTC + (n - OUTC)];
        bsplit(bc, d_BcThi[idx], d_BcTlo[idx]);
    }
    if (idx < 256) d_bcat[idx] = (idx < OUTC) ? bmu[idx] : bls[idx - OUTC];
}

// ---------------- aggregation (gather via CSR, node range [n0, n1)) ----------
// BUF=0: d_h0 -> d_h (relu+bias). BUF=1: d_h -> (d_ghi, d_glo).
// block (64,4): 4 nodes/block, 64 lanes x float4 cover all 256 features.
template <int BUF>
__global__ __launch_bounds__(256) void k_agg(const float* __restrict__ bias,
                                             int n0, int n1) {
    int node = n0 + blockIdx.x * 4 + threadIdx.y;
    if (node >= n1) return;
    int f4 = threadIdx.x;  // 0..63
    const float4* sf = (BUF == 0) ? (const float4*)d_h0 : (const float4*)d_h;

    float di = d_dinv[node];
    float w0 = di * di;
    float4 acc = sf[(size_t)node * 64 + f4];
    acc.x *= w0; acc.y *= w0; acc.z *= w0; acc.w *= w0;

    int beg = d_rowptr[node], end = d_rowptr[node + 1];
    int e = beg;
    for (; e + 4 <= end; e += 4) {
        int2 c0 = d_csr[e];
        int2 c1 = d_csr[e + 1];
        int2 c2 = d_csr[e + 2];
        int2 c3 = d_csr[e + 3];
        float4 v0 = sf[(size_t)c0.x * 64 + f4];
        float4 v1 = sf[(size_t)c1.x * 64 + f4];
        float4 v2 = sf[(size_t)c2.x * 64 + f4];
        float4 v3 = sf[(size_t)c3.x * 64 + f4];
        float w0f = __int_as_float(c0.y), w1f = __int_as_float(c1.y);
        float w2f = __int_as_float(c2.y), w3f = __int_as_float(c3.y);
        acc.x += w0f * v0.x + w1f * v1.x + w2f * v2.x + w3f * v3.x;
        acc.y += w0f * v0.y + w1f * v1.y + w2f * v2.y + w3f * v3.y;
        acc.z += w0f * v0.z + w1f * v1.z + w2f * v2.z + w3f * v3.z;
        acc.w += w0f * v0.w + w1f * v1.w + w2f * v2.w + w3f * v3.w;
    }
    for (; e < end; e++) {
        int2 c = d_csr[e];
        float w = __int_as_float(c.y);
        float4 v = sf[(size_t)c.x * 64 + f4];
        acc.x += w * v.x;
        acc.y += w * v.y;
        acc.z += w * v.z;
        acc.w += w * v.w;
    }
    if (BUF == 0) {
        float4 b = ((const float4*)bias)[f4];
        acc.x = fmaxf(acc.x + b.x, 0.f);
        acc.y = fmaxf(acc.y + b.y, 0.f);
        acc.z = fmaxf(acc.z + b.z, 0.f);
        acc.w = fmaxf(acc.w + b.w, 0.f);
        ((float4*)d_h)[(size_t)node * 64 + f4] = acc;
    } else {
        uint2 hv, lv;
        split2(acc.x, acc.y, hv.x, lv.x);
        split2(acc.z, acc.w, hv.y, lv.y);
        *(uint2*)&d_ghi[(size_t)node * 256 + f4 * 4] = hv;
        *(uint2*)&d_glo[(size_t)node * 256 + f4 * 4] = lv;
    }
}

// ---------------- mma.sync bf16-split GEMM ----------------
// MODE 0: h0 = x @ W1^T, full K=256, grid (2, 391), m0=0.
// MODE 1: [mu|ls] = g @ Bc^T + bias, rows [m0, m0+128*grid.y), grid (2, *).
#define TILE_B 16384
#define GSMEM  (4 * TILE_B)

__device__ __forceinline__ void load_tile64(char* tile, const __nv_bfloat16* __restrict__ src,
                                            int row0, int nvalid, int col0) {
    int t = threadIdx.x;
    int r = t >> 1;
    int hb = (t & 1) * 64;
    const char* srow = (const char*)(src + (size_t)(row0 + r) * 256 + col0);
    bool valid = r < nvalid;
#pragma unroll
    for (int i = 0; i < 4; i++) {
        int b = hb + i * 16;
        uint4 v = valid ? *(const uint4*)(srow + b) : make_uint4(0u, 0u, 0u, 0u);
        uint32_t off = (uint32_t)(r * 128 + b);
        off ^= ((off >> 3) & 0x70);
        *(uint4*)(tile + off) = v;
    }
}

__device__ __forceinline__ void load_tile64_split(char* tilehi, char* tilelo,
                                                  const float* __restrict__ src,
                                                  int row0, int nvalid, int col0) {
    int t = threadIdx.x;
    int r = t >> 1;
    int hf = (t & 1) * 32;
    const float* srow = src + (size_t)(row0 + r) * 256 + col0 + hf;
    bool valid = r < nvalid;
#pragma unroll
    for (int i = 0; i < 4; i++) {
        float4 f0 = valid ? *(const float4*)(srow + i * 8)     : make_float4(0.f, 0.f, 0.f, 0.f);
        float4 f1 = valid ? *(const float4*)(srow + i * 8 + 4) : make_float4(0.f, 0.f, 0.f, 0.f);
        uint4 hv, lv;
        split2(f0.x, f0.y, hv.x, lv.x);
        split2(f0.z, f0.w, hv.y, lv.y);
        split2(f1.x, f1.y, hv.z, lv.z);
        split2(f1.z, f1.w, hv.w, lv.w);
        uint32_t off = (uint32_t)(r * 128 + hf * 2 + i * 16);
        off ^= ((off >> 3) & 0x70);
        *(uint4*)(tilehi + off) = hv;
        *(uint4*)(tilelo + off) = lv;
    }
}

template <int MODE>
__global__ __launch_bounds__(256) void k_gemm_mma(const float* __restrict__ Ax,
                                                  float* __restrict__ Cp, int m0) {
    extern __shared__ char smem[];
    char* sAhi = smem;
    char* sAlo = smem + TILE_B;
    char* sBhi = smem + 2 * TILE_B;
    char* sBlo = smem + 3 * TILE_B;
    uint32_t bAhi = smem_u32(sAhi), bAlo = bAhi + TILE_B;
    uint32_t bBhi = bAhi + 2 * TILE_B, bBlo = bAhi + 3 * TILE_B;

    int tid = threadIdx.x, wid = tid >> 5, lane = tid & 31;
    int wm = wid >> 1, wn = wid & 1;
    int bn = blockIdx.x * 128;
    int bm = m0 + blockIdx.y * 128;

    const __nv_bfloat16* Bhi = (MODE == 0) ? d_W1Thi : d_BcThi;
    const __nv_bfloat16* Blo = (MODE == 0) ? d_W1Tlo : d_BcTlo;

    int navalid = NN - bm; if (navalid > 128) navalid = 128;

    float acc[2][8][4];
#pragma unroll
    for (int i = 0; i < 2; i++)
#pragma unroll
        for (int j = 0; j < 8; j++)
#pragma unroll
            for (int q = 0; q < 4; q++) acc[i][j][q] = 0.f;

    int a_row_off = ((lane >> 3) & 1) * 8 + (lane & 7);
    int a_kc_off  = (lane >> 4);
    int b_row_off = (lane >> 4) * 8 + (lane & 7);
    int b_kc_off  = ((lane >> 3) & 1);

    for (int c = 0; c < 4; c++) {
        if (c > 0) __syncthreads();
        if (MODE == 0) {
            load_tile64_split(sAhi, sAlo, Ax, bm, navalid, c * 64);
        } else {
            load_tile64(sAhi, d_ghi, bm, navalid, c * 64);
            load_tile64(sAlo, d_glo, bm, navalid, c * 64);
        }
        load_tile64(sBhi, Bhi, bn, 128, c * 64);
        load_tile64(sBlo, Blo, bn, 128, c * 64);
        __syncthreads();

#pragma unroll
        for (int ks = 0; ks < 4; ks++) {
            int kc0 = ks * 2;
            uint32_t ahi[2][4], alo[2][4];
#pragma unroll
            for (int mi = 0; mi < 2; mi++) {
                int row = wm * 32 + mi * 16 + a_row_off;
                int kc  = kc0 + a_kc_off;
                ldmat_x4(ahi[mi][0], ahi[mi][1], ahi[mi][2], ahi[mi][3],
                         sw_addr(bAhi, row, kc));
                ldmat_x4(alo[mi][0], alo[mi][1], alo[mi][2], alo[mi][3],
                         sw_addr(bAlo, row, kc));
            }
#pragma unroll
            for (int ng = 0; ng < 4; ng++) {
                int nrow = wn * 64 + ng * 16 + b_row_off;
                int kc   = kc0 + b_kc_off;
                uint32_t bh[4], bl[4];
                ldmat_x4(bh[0], bh[1], bh[2], bh[3], sw_addr(bBhi, nrow, kc));
                ldmat_x4(bl[0], bl[1], bl[2], bl[3], sw_addr(bBlo, nrow, kc));
#pragma unroll
                for (int mi = 0; mi < 2; mi++) {
                    mma_bf16(acc[mi][ng * 2],     ahi[mi], bh[0], bh[1]);
                    mma_bf16(acc[mi][ng * 2],     ahi[mi], bl[0], bl[1]);
                    mma_bf16(acc[mi][ng * 2],     alo[mi], bh[0], bh[1]);
                    mma_bf16(acc[mi][ng * 2 + 1], ahi[mi], bh[2], bh[3]);
                    mma_bf16(acc[mi][ng * 2 + 1], ahi[mi], bl[2], bl[3]);
                    mma_bf16(acc[mi][ng * 2 + 1], alo[mi], bh[2], bh[3]);
                }
            }
        }
    }

#pragma unroll
    for (int mi = 0; mi < 2; mi++) {
        int r0 = bm + wm * 32 + mi * 16 + (lane >> 2);
#pragma unroll
        for (int ni = 0; ni < 8; ni++) {
            int col = wn * 64 + ni * 8 + (lane & 3) * 2;
            float* a = acc[mi][ni];
            if (MODE == 0) {
                if (r0 < NN)
                    *(float2*)&d_h0[(size_t)r0 * 256 + bn + col] = make_float2(a[0], a[1]);
                if (r0 + 8 < NN)
                    *(float2*)&d_h0[(size_t)(r0 + 8) * 256 + bn + col] = make_float2(a[2], a[3]);
            } else {
                float bx = d_bcat[bn + col], by = d_bcat[bn + col + 1];
                size_t half = (bn == 0) ? 0 : (size_t)NN * OUTC;
                if (r0 < NN)
                    *(float2*)&Cp[half + (size_t)r0 * OUTC + col] =
                        make_float2(a[0] + bx, a[1] + by);
                if (r0 + 8 < NN)
                    *(float2*)&Cp[half + (size_t)(r0 + 8) * OUTC + col] =
                        make_float2(a[2] + bx, a[3] + by);
            }
        }
    }
}

// ---------------- launch ----------------
extern "C" void kernel_launch(void* const* d_in, const int* in_sizes, int n_in,
                              void* d_out, int out_size) {
    const float* x   = (const float*)d_in[0];
    const void*  ei  = d_in[1];
    const float* W1  = (const float*)d_in[2];
    const float* b1  = (const float*)d_in[3];
    const float* Wmu = (const float*)d_in[4];
    const float* bmu = (const float*)d_in[5];
    const float* Wls = (const float*)d_in[6];
    const float* bls = (const float*)d_in[7];
    float* out = (float*)d_out;

    cudaFuncSetAttribute(k_gemm_mma<0>, cudaFuncAttributeMaxDynamicSharedMemorySize, GSMEM);
    cudaFuncSetAttribute(k_gemm_mma<1>, cudaFuncAttributeMaxDynamicSharedMemorySize, GSMEM);

    dim3 ggrid0(2, (NN + 127) / 128);          // GEMM0 full
    dim3 ggrid1a(2, MSPLIT / 128);             // GEMM1 rows [0, MSPLIT)
    dim3 ggrid1b(2, (NN - MSPLIT + 127) / 128);// GEMM1 rows [MSPLIT, NN)
    dim3 agrid0((NN + 3) / 4);
    dim3 agrid1a((MSPLIT + 3) / 4);
    dim3 agrid1b((NN - MSPLIT + 3) / 4);
    dim3 ablk(64, 4);

    cudaStream_t s1;
    cudaStreamCreateWithFlags(&s1, cudaStreamNonBlocking);
    cudaEvent_t e0, eG0, eA1a, eG1a;
    cudaEventCreateWithFlags(&e0,   cudaEventDisableTiming);
    cudaEventCreateWithFlags(&eG0,  cudaEventDisableTiming);
    cudaEventCreateWithFlags(&eA1a, cudaEventDisableTiming);
    cudaEventCreateWithFlags(&eG1a, cudaEventDisableTiming);

    cudaEventRecord(e0, 0);
    cudaStreamWaitEvent(s1, e0, 0);

    // branch B (s1): pack weights, then GEMM0 (x @ W1 -> d_h0)
    k_pack2<<<(65536 + 255) / 256, 256, 0, s1>>>(W1, Wmu, Wls, bmu, bls);
    k_gemm_mma<0><<<ggrid0, 256, GSMEM, s1>>>(x, nullptr, 0);
    cudaEventRecord(eG0, s1);

    // branch A (stream 0): CSR build
    k_zero<<<(NN + 255) / 256, 256>>>((const unsigned long long*)ei);
    k_count<<<(EE + 255) / 256, 256>>>(ei);
    k_scan1<<<NB_S, 512>>>();
    k_scan2<<<1, 128>>>();
    k_scan3<<<NB_S, 512>>>();
    k_fill<<<(EE + 255) / 256, 256>>>(ei);

    // join: agg0 needs d_h0 + CSR
    cudaStreamWaitEvent(0, eG0, 0);
    k_agg<0><<<agrid0, ablk>>>(b1, 0, NN);

    // agg1 first node-chunk, then GEMM1a on s1 overlapping agg1b
    k_agg<1><<<agrid1a, ablk>>>(nullptr, 0, MSPLIT);
    cudaEventRecord(eA1a, 0);
    cudaStreamWaitEvent(s1, eA1a, 0);
    k_gemm_mma<1><<<ggrid1a, 256, GSMEM, s1>>>(nullptr, out, 0);
    cudaEventRecord(eG1a, s1);

    k_agg<1><<<agrid1b, ablk>>>(nullptr, MSPLIT, NN);
    // rejoin side-stream before the final launch (disjoint rows, but keeps the
    // captured graph's last node a kernel, not a dangling wait)
    cudaStreamWaitEvent(0, eG1a, 0);
    k_gemm_mma<1><<<ggrid1b, 256, GSMEM>>>(nullptr, out, MSPLIT);
}

// round 13
// speedup vs baseline: 1.3760x; 1.2104x over previous
#include <cuda_runtime.h>
#include <cuda_bf16.h>
#include <cuda_fp16.h>
#include <cstdint>

#define NN   50000
#define EE   800000
#define HIDC 256
#define OUTC 128
#define NB_S 98   // ceil(NN/512)

// ---------------- scratch (static device globals; no allocation) ----------------
__device__ int   d_is64;
__device__ int   d_deg[NN];
__device__ float d_dinv[NN];
__device__ int   d_rowptr[NN + 1];
__device__ int   d_cursor[NN];
__device__ int   d_bsum[NB_S];
__device__ int   d_boff[NB_S];
__device__ int2  d_csr[EE];                    // (src, w as float bits)
__device__ __half d_h0f16[(size_t)NN * HIDC];  // x @ W1 (fp16 storage)
__device__ __half d_hf16 [(size_t)NN * HIDC];  // relu(Agg(h0) + b1) (fp16 storage)
__device__ __nv_bfloat16 d_ghi[(size_t)NN * HIDC];  // split of Agg(h)
__device__ __nv_bfloat16 d_glo[(size_t)NN * HIDC];
__device__ __nv_bfloat16 d_W1Thi[HIDC * HIDC];  // W1^T  [n][k]
__device__ __nv_bfloat16 d_W1Tlo[HIDC * HIDC];
__device__ __nv_bfloat16 d_BcThi[HIDC * HIDC];  // [Wmu|Wls]^T  [n][k]
__device__ __nv_bfloat16 d_BcTlo[HIDC * HIDC];
__device__ float d_bcat[256];                   // [b_mu | b_ls]

// ---------------- helpers ----------------
__device__ __forceinline__ uint32_t smem_u32(const void* p) {
    uint32_t a;
    asm("{ .reg .u64 t; cvta.to.shared.u64 t, %1; cvt.u32.u64 %0, t; }" : "=r"(a) : "l"(p));
    return a;
}
__device__ __forceinline__ void bsplit(float v, __nv_bfloat16& h, __nv_bfloat16& l) {
    h = __float2bfloat16(v);
    l = __float2bfloat16(v - __bfloat162float(h));
}
__device__ __forceinline__ void split2(float a, float b, uint32_t& h, uint32_t& l) {
    __nv_bfloat16 ha, la, hb, lb;
    bsplit(a, ha, la);
    bsplit(b, hb, lb);
    h = (uint32_t)__bfloat16_as_ushort(ha) | ((uint32_t)__bfloat16_as_ushort(hb) << 16);
    l = (uint32_t)__bfloat16_as_ushort(la) | ((uint32_t)__bfloat16_as_ushort(lb) << 16);
}
__device__ __forceinline__ void ldmat_x4(uint32_t& r0, uint32_t& r1, uint32_t& r2,
                                         uint32_t& r3, uint32_t addr) {
    asm volatile("ldmatrix.sync.aligned.m8n8.x4.shared.b16 {%0,%1,%2,%3}, [%4];"
                 : "=r"(r0), "=r"(r1), "=r"(r2), "=r"(r3) : "r"(addr));
}
__device__ __forceinline__ void mma_bf16(float* c, const uint32_t* a,
                                         uint32_t b0, uint32_t b1) {
    asm volatile("mma.sync.aligned.m16n8k16.row.col.f32.bf16.bf16.f32 "
                 "{%0,%1,%2,%3}, {%4,%5,%6,%7}, {%8,%9}, {%0,%1,%2,%3};"
                 : "+f"(c[0]), "+f"(c[1]), "+f"(c[2]), "+f"(c[3])
                 : "r"(a[0]), "r"(a[1]), "r"(a[2]), "r"(a[3]), "r"(b0), "r"(b1));
}
__device__ __forceinline__ uint32_t sw_addr(uint32_t base, int row, int kc) {
    return base + row * 128 + ((kc ^ (row & 7)) << 4);
}
__device__ __forceinline__ int load_idx(const void* ei, size_t pos) {
    if (d_is64) return (int)((const long long*)ei)[pos];
    return ((const int*)ei)[pos];
}
// fma of 8 fp16 values (packed in uint4) into 8 fp32 accumulators
__device__ __forceinline__ void fma8(float* acc, uint4 v, float w) {
    __half2* h = (__half2*)&v;
#pragma unroll
    for (int i = 0; i < 4; i++) {
        float2 f = __half22float2(h[i]);
        acc[2 * i]     += w * f.x;
        acc[2 * i + 1] += w * f.y;
    }
}

// ---------------- setup kernels ----------------
__global__ void k_zero(const unsigned long long* __restrict__ ei) {
    int i = blockIdx.x * 256 + threadIdx.x;
    if (i < NN) d_deg[i] = 0;
    if (i == 0) {
        int is64 = 1;
        for (int j = 0; j < 128; j++)
            if (ei[j] >= (1ull << 32)) { is64 = 0; break; }
        d_is64 = is64;
    }
}
__global__ void k_count(const void* __restrict__ ei) {
    int e = blockIdx.x * 256 + threadIdx.x;
    if (e < EE) atomicAdd(&d_deg[load_idx(ei, (size_t)EE + e)], 1);
}
// ---- 3-phase parallel scan (edge-only counts; self-loop via +1 in dinv)
__global__ __launch_bounds__(512) void k_scan1() {
    __shared__ int sw[16];
    int b = blockIdx.x, tid = threadIdx.x;
    int i = b * 512 + tid;
    int lane = tid & 31, wid = tid >> 5;
    int deg = (i < NN) ? d_deg[i] : 0;
    if (i < NN) d_dinv[i] = rsqrtf((float)(deg + 1));
    int x = deg;
#pragma unroll
    for (int d = 1; d < 32; d <<= 1) {
        int t = __shfl_up_sync(0xffffffffu, x, d);
        if (lane >= d) x += t;
    }
    if (lane == 31) sw[wid] = x;
    __syncthreads();
    if (wid == 0 && lane < 16) {
        int y = sw[lane];
#pragma unroll
        for (int d = 1; d < 16; d <<= 1) {
            int t = __shfl_up_sync(0xffffu, y, d);
            if (lane >= d) y += t;
        }
        sw[lane] = y;
    }
    __syncthreads();
    int incl = x + ((wid > 0) ? sw[wid - 1] : 0);
    if (i < NN) d_rowptr[i + 1] = incl;
    if (tid == 511) d_bsum[b] = incl;
}
__global__ __launch_bounds__(128) void k_scan2() {
    __shared__ int sw[4];
    int tid = threadIdx.x, lane = tid & 31, wid = tid >> 5;
    int v = (tid < NB_S) ? d_bsum[tid] : 0;
    int x = v;
#pragma unroll
    for (int d = 1; d < 32; d <<= 1) {
        int t = __shfl_up_sync(0xffffffffu, x, d);
        if (lane >= d) x += t;
    }
    if (lane == 31) sw[wid] = x;
    __syncthreads();
    if (wid == 0 && lane < 4) {
        int y = sw[lane];
#pragma unroll
        for (int d = 1; d < 4; d <<= 1) {
            int t = __shfl_up_sync(0xfu, y, d);
            if (lane >= d) y += t;
        }
        sw[lane] = y;
    }
    __syncthreads();
    int incl = x + ((wid > 0) ? sw[wid - 1] : 0);
    if (tid < NB_S) d_boff[tid] = incl - v;  // exclusive
}
__global__ __launch_bounds__(512) void k_scan3() {
    int i = blockIdx.x * 512 + threadIdx.x;
    if (i < NN) {
        int r = d_rowptr[i + 1] + d_boff[i >> 9];
        d_rowptr[i + 1] = r;
        d_cursor[i]     = r - d_deg[i];
    }
    if (i == 0) d_rowptr[0] = 0;
}
__global__ void k_fill(const void* __restrict__ ei) {
    int e = blockIdx.x * 256 + threadIdx.x;
    if (e < EE) {
        int s = load_idx(ei, (size_t)e);
        int d = load_idx(ei, (size_t)EE + e);
        int pos = atomicAdd(&d_cursor[d], 1);
        d_csr[pos] = make_int2(s, __float_as_int(d_dinv[s] * d_dinv[d]));
    }
}

// pack + transpose + bf16-split the weights
__global__ void k_pack2(const float* __restrict__ W1,
                        const float* __restrict__ Wmu, const float* __restrict__ Wls,
                        const float* __restrict__ bmu, const float* __restrict__ bls) {
    int idx = blockIdx.x * 256 + threadIdx.x;
    if (idx < 65536) {
        int n = idx >> 8, k = idx & 255;
        bsplit(W1[k * 256 + n], d_W1Thi[idx], d_W1Tlo[idx]);
        float bc = (n < OUTC) ? Wmu[k * OUTC + n] : Wls[k * OUTC + (n - OUTC)];
        bsplit(bc, d_BcThi[idx], d_BcTlo[idx]);
    }
    if (idx < 256) d_bcat[idx] = (idx < OUTC) ? bmu[idx] : bls[idx - OUTC];
}

// ---------------- aggregation (fp16 gather via CSR, fp32 accumulate) ----------
// BUF=0: d_h0f16 -> d_hf16 (relu+bias). BUF=1: d_hf16 -> (d_ghi, d_glo).
// block (32,8): 8 nodes/block, 32 lanes x uint4(8 halves) cover 256 features.
template <int BUF>
__global__ __launch_bounds__(256) void k_agg(const float* __restrict__ bias) {
    int node = blockIdx.x * 8 + threadIdx.y;
    if (node >= NN) return;
    int lane = threadIdx.x;  // 0..31, handles features [lane*8, lane*8+8)
    const uint4* sf = (BUF == 0) ? (const uint4*)d_h0f16 : (const uint4*)d_hf16;

    float di = d_dinv[node];
    float w0 = di * di;
    float acc[8];
    {
        uint4 v = sf[(size_t)node * 32 + lane];
        __half2* h = (__half2*)&v;
#pragma unroll
        for (int i = 0; i < 4; i++) {
            float2 f = __half22float2(h[i]);
            acc[2 * i]     = w0 * f.x;
            acc[2 * i + 1] = w0 * f.y;
        }
    }

    int beg = d_rowptr[node], end = d_rowptr[node + 1];
    int e = beg;
    for (; e + 4 <= end; e += 4) {
        int2 c0 = d_csr[e];
        int2 c1 = d_csr[e + 1];
        int2 c2 = d_csr[e + 2];
        int2 c3 = d_csr[e + 3];
        uint4 v0 = sf[(size_t)c0.x * 32 + lane];
        uint4 v1 = sf[(size_t)c1.x * 32 + lane];
        uint4 v2 = sf[(size_t)c2.x * 32 + lane];
        uint4 v3 = sf[(size_t)c3.x * 32 + lane];
        fma8(acc, v0, __int_as_float(c0.y));
        fma8(acc, v1, __int_as_float(c1.y));
        fma8(acc, v2, __int_as_float(c2.y));
        fma8(acc, v3, __int_as_float(c3.y));
    }
    for (; e < end; e++) {
        int2 c = d_csr[e];
        uint4 v = sf[(size_t)c.x * 32 + lane];
        fma8(acc, v, __int_as_float(c.y));
    }

    if (BUF == 0) {
        const float4* b4 = (const float4*)bias;
        float4 ba = b4[lane * 2];
        float4 bb = b4[lane * 2 + 1];
        float bv[8] = {ba.x, ba.y, ba.z, ba.w, bb.x, bb.y, bb.z, bb.w};
        uint4 outv;
        __half2* oh = (__half2*)&outv;
#pragma unroll
        for (int i = 0; i < 4; i++) {
            float fx = fmaxf(acc[2 * i]     + bv[2 * i],     0.f);
            float fy = fmaxf(acc[2 * i + 1] + bv[2 * i + 1], 0.f);
            oh[i] = __floats2half2_rn(fx, fy);
        }
        ((uint4*)d_hf16)[(size_t)node * 32 + lane] = outv;
    } else {
        uint4 hv, lv;
        split2(acc[0], acc[1], hv.x, lv.x);
        split2(acc[2], acc[3], hv.y, lv.y);
        split2(acc[4], acc[5], hv.z, lv.z);
        split2(acc[6], acc[7], hv.w, lv.w);
        *(uint4*)&d_ghi[(size_t)node * 256 + lane * 8] = hv;
        *(uint4*)&d_glo[(size_t)node * 256 + lane * 8] = lv;
    }
}

// ---------------- mma.sync bf16-split GEMM ----------------
// MODE 0: h0f16 = x @ W1^T (fp16 store), grid (2, 391).
// MODE 1: [mu|ls] = g @ Bc^T + bias -> out, grid (2, 391).
#define TILE_B 16384
#define GSMEM  (4 * TILE_B)

__device__ __forceinline__ void load_tile64(char* tile, const __nv_bfloat16* __restrict__ src,
                                            int row0, int nvalid, int col0) {
    int t = threadIdx.x;
    int r = t >> 1;
    int hb = (t & 1) * 64;
    const char* srow = (const char*)(src + (size_t)(row0 + r) * 256 + col0);
    bool valid = r < nvalid;
#pragma unroll
    for (int i = 0; i < 4; i++) {
        int b = hb + i * 16;
        uint4 v = valid ? *(const uint4*)(srow + b) : make_uint4(0u, 0u, 0u, 0u);
        uint32_t off = (uint32_t)(r * 128 + b);
        off ^= ((off >> 3) & 0x70);
        *(uint4*)(tile + off) = v;
    }
}

__device__ __forceinline__ void load_tile64_split(char* tilehi, char* tilelo,
                                                  const float* __restrict__ src,
                                                  int row0, int nvalid, int col0) {
    int t = threadIdx.x;
    int r = t >> 1;
    int hf = (t & 1) * 32;
    const float* srow = src + (size_t)(row0 + r) * 256 + col0 + hf;
    bool valid = r < nvalid;
#pragma unroll
    for (int i = 0; i < 4; i++) {
        float4 f0 = valid ? *(const float4*)(srow + i * 8)     : make_float4(0.f, 0.f, 0.f, 0.f);
        float4 f1 = valid ? *(const float4*)(srow + i * 8 + 4) : make_float4(0.f, 0.f, 0.f, 0.f);
        uint4 hv, lv;
        split2(f0.x, f0.y, hv.x, lv.x);
        split2(f0.z, f0.w, hv.y, lv.y);
        split2(f1.x, f1.y, hv.z, lv.z);
        split2(f1.z, f1.w, hv.w, lv.w);
        uint32_t off = (uint32_t)(r * 128 + hf * 2 + i * 16);
        off ^= ((off >> 3) & 0x70);
        *(uint4*)(tilehi + off) = hv;
        *(uint4*)(tilelo + off) = lv;
    }
}

template <int MODE>
__global__ __launch_bounds__(256) void k_gemm_mma(const float* __restrict__ Ax,
                                                  float* __restrict__ Cp) {
    extern __shared__ char smem[];
    char* sAhi = smem;
    char* sAlo = smem + TILE_B;
    char* sBhi = smem + 2 * TILE_B;
    char* sBlo = smem + 3 * TILE_B;
    uint32_t bAhi = smem_u32(sAhi), bAlo = bAhi + TILE_B;
    uint32_t bBhi = bAhi + 2 * TILE_B, bBlo = bAhi + 3 * TILE_B;

    int tid = threadIdx.x, wid = tid >> 5, lane = tid & 31;
    int wm = wid >> 1, wn = wid & 1;
    int bn = blockIdx.x * 128;
    int bm = blockIdx.y * 128;

    const __nv_bfloat16* Bhi = (MODE == 0) ? d_W1Thi : d_BcThi;
    const __nv_bfloat16* Blo = (MODE == 0) ? d_W1Tlo : d_BcTlo;

    int navalid = NN - bm; if (navalid > 128) navalid = 128;

    float acc[2][8][4];
#pragma unroll
    for (int i = 0; i < 2; i++)
#pragma unroll
        for (int j = 0; j < 8; j++)
#pragma unroll
            for (int q = 0; q < 4; q++) acc[i][j][q] = 0.f;

    int a_row_off = ((lane >> 3) & 1) * 8 + (lane & 7);
    int a_kc_off  = (lane >> 4);
    int b_row_off = (lane >> 4) * 8 + (lane & 7);
    int b_kc_off  = ((lane >> 3) & 1);

    for (int c = 0; c < 4; c++) {
        if (c > 0) __syncthreads();
        if (MODE == 0) {
            load_tile64_split(sAhi, sAlo, Ax, bm, navalid, c * 64);
        } else {
            load_tile64(sAhi, d_ghi, bm, navalid, c * 64);
            load_tile64(sAlo, d_glo, bm, navalid, c * 64);
        }
        load_tile64(sBhi, Bhi, bn, 128, c * 64);
        load_tile64(sBlo, Blo, bn, 128, c * 64);
        __syncthreads();

#pragma unroll
        for (int ks = 0; ks < 4; ks++) {
            int kc0 = ks * 2;
            uint32_t ahi[2][4], alo[2][4];
#pragma unroll
            for (int mi = 0; mi < 2; mi++) {
                int row = wm * 32 + mi * 16 + a_row_off;
                int kc  = kc0 + a_kc_off;
                ldmat_x4(ahi[mi][0], ahi[mi][1], ahi[mi][2], ahi[mi][3],
                         sw_addr(bAhi, row, kc));
                ldmat_x4(alo[mi][0], alo[mi][1], alo[mi][2], alo[mi][3],
                         sw_addr(bAlo, row, kc));
            }
#pragma unroll
            for (int ng = 0; ng < 4; ng++) {
                int nrow = wn * 64 + ng * 16 + b_row_off;
                int kc   = kc0 + b_kc_off;
                uint32_t bh[4], bl[4];
                ldmat_x4(bh[0], bh[1], bh[2], bh[3], sw_addr(bBhi, nrow, kc));
                ldmat_x4(bl[0], bl[1], bl[2], bl[3], sw_addr(bBlo, nrow, kc));
#pragma unroll
                for (int mi = 0; mi < 2; mi++) {
                    mma_bf16(acc[mi][ng * 2],     ahi[mi], bh[0], bh[1]);
                    mma_bf16(acc[mi][ng * 2],     ahi[mi], bl[0], bl[1]);
                    mma_bf16(acc[mi][ng * 2],     alo[mi], bh[0], bh[1]);
                    mma_bf16(acc[mi][ng * 2 + 1], ahi[mi], bh[2], bh[3]);
                    mma_bf16(acc[mi][ng * 2 + 1], ahi[mi], bl[2], bl[3]);
                    mma_bf16(acc[mi][ng * 2 + 1], alo[mi], bh[2], bh[3]);
                }
            }
        }
    }

#pragma unroll
    for (int mi = 0; mi < 2; mi++) {
        int r0 = bm + wm * 32 + mi * 16 + (lane >> 2);
#pragma unroll
        for (int ni = 0; ni < 8; ni++) {
            int col = wn * 64 + ni * 8 + (lane & 3) * 2;
            float* a = acc[mi][ni];
            if (MODE == 0) {
                if (r0 < NN)
                    *(__half2*)&d_h0f16[(size_t)r0 * 256 + bn + col] =
                        __floats2half2_rn(a[0], a[1]);
                if (r0 + 8 < NN)
                    *(__half2*)&d_h0f16[(size_t)(r0 + 8) * 256 + bn + col] =
                        __floats2half2_rn(a[2], a[3]);
            } else {
                float bx = d_bcat[bn + col], by = d_bcat[bn + col + 1];
                size_t half_off = (bn == 0) ? 0 : (size_t)NN * OUTC;
                if (r0 < NN)
                    *(float2*)&Cp[half_off + (size_t)r0 * OUTC + col] =
                        make_float2(a[0] + bx, a[1] + by);
                if (r0 + 8 < NN)
                    *(float2*)&Cp[half_off + (size_t)(r0 + 8) * OUTC + col] =
                        make_float2(a[2] + bx, a[3] + by);
            }
        }
    }
}

// ---------------- launch ----------------
extern "C" void kernel_launch(void* const* d_in, const int* in_sizes, int n_in,
                              void* d_out, int out_size) {
    const float* x   = (const float*)d_in[0];
    const void*  ei  = d_in[1];
    const float* W1  = (const float*)d_in[2];
    const float* b1  = (const float*)d_in[3];
    const float* Wmu = (const float*)d_in[4];
    const float* bmu = (const float*)d_in[5];
    const float* Wls = (const float*)d_in[6];
    const float* bls = (const float*)d_in[7];
    float* out = (float*)d_out;

    cudaFuncSetAttribute(k_gemm_mma<0>, cudaFuncAttributeMaxDynamicSharedMemorySize, GSMEM);
    cudaFuncSetAttribute(k_gemm_mma<1>, cudaFuncAttributeMaxDynamicSharedMemorySize, GSMEM);

    dim3 ggrid(2, (NN + 127) / 128);
    dim3 agrid((NN + 7) / 8);
    dim3 ablk(32, 8);

    cudaStream_t s1;
    cudaStreamCreateWithFlags(&s1, cudaStreamNonBlocking);
    cudaEvent_t e0, eG0;
    cudaEventCreateWithFlags(&e0,  cudaEventDisableTiming);
    cudaEventCreateWithFlags(&eG0, cudaEventDisableTiming);

    cudaEventRecord(e0, 0);
    cudaStreamWaitEvent(s1, e0, 0);

    // branch B (s1): pack weights, then GEMM0 (x @ W1 -> d_h0f16)
    k_pack2<<<(65536 + 255) / 256, 256, 0, s1>>>(W1, Wmu, Wls, bmu, bls);
    k_gemm_mma<0><<<ggrid, 256, GSMEM, s1>>>(x, nullptr);
    cudaEventRecord(eG0, s1);

    // branch A (stream 0): CSR build
    k_zero<<<(NN + 255) / 256, 256>>>((const unsigned long long*)ei);
    k_count<<<(EE + 255) / 256, 256>>>(ei);
    k_scan1<<<NB_S, 512>>>();
    k_scan2<<<1, 128>>>();
    k_scan3<<<NB_S, 512>>>();
    k_fill<<<(EE + 255) / 256, 256>>>(ei);

    // join: agg0 needs d_h0f16 + CSR
    cudaStreamWaitEvent(0, eG0, 0);
    k_agg<0><<<agrid, ablk>>>(b1);
    k_agg<1><<<agrid, ablk>>>(nullptr);
    k_gemm_mma<1><<<ggrid, 256, GSMEM>>>(nullptr, out);
}

// round 14
// speedup vs baseline: 2.1522x; 1.5641x over previous
#include <cuda_runtime.h>
#include <cuda_bf16.h>
#include <cuda_fp16.h>
#include <cstdint>

#define NN   50000
#define EE   800000
#define HIDC 256
#define OUTC 128
#define NB_S 98   // ceil(NN/512)

// ---------------- scratch (static device globals; no allocation) ----------------
__device__ int   d_is64;
__device__ int   d_deg[NN];
__device__ float d_dinv[NN];
__device__ int   d_rowptr[NN + 1];
__device__ int   d_cursor[NN];
__device__ int   d_bsum[NB_S];
__device__ int   d_boff[NB_S];
__device__ int2  d_csr[EE];                    // (src, w as float bits)
__device__ __half d_h0f16[(size_t)NN * HIDC];  // x @ W1 (fp16)
__device__ __half d_hf16 [(size_t)NN * HIDC];  // relu(Agg(h0) + b1) (fp16)
__device__ __half d_gf16 [(size_t)NN * HIDC];  // Agg(h) (fp16)
__device__ __half d_W1Tf16[HIDC * HIDC];       // W1^T  [n][k] fp16
__device__ __half d_BcTf16[HIDC * HIDC];       // [Wmu|Wls]^T [n][k] fp16
__device__ float d_bcat[256];                  // [b_mu | b_ls]

// ---------------- helpers ----------------
__device__ __forceinline__ uint32_t smem_u32(const void* p) {
    uint32_t a;
    asm("{ .reg .u64 t; cvta.to.shared.u64 t, %1; cvt.u32.u64 %0, t; }" : "=r"(a) : "l"(p));
    return a;
}
__device__ __forceinline__ void ldmat_x4(uint32_t& r0, uint32_t& r1, uint32_t& r2,
                                         uint32_t& r3, uint32_t addr) {
    asm volatile("ldmatrix.sync.aligned.m8n8.x4.shared.b16 {%0,%1,%2,%3}, [%4];"
                 : "=r"(r0), "=r"(r1), "=r"(r2), "=r"(r3) : "r"(addr));
}
__device__ __forceinline__ void mma_f16(float* c, const uint32_t* a,
                                        uint32_t b0, uint32_t b1) {
    asm volatile("mma.sync.aligned.m16n8k16.row.col.f32.f16.f16.f32 "
                 "{%0,%1,%2,%3}, {%4,%5,%6,%7}, {%8,%9}, {%0,%1,%2,%3};"
                 : "+f"(c[0]), "+f"(c[1]), "+f"(c[2]), "+f"(c[3])
                 : "r"(a[0]), "r"(a[1]), "r"(a[2]), "r"(a[3]), "r"(b0), "r"(b1));
}
__device__ __forceinline__ uint32_t sw_addr(uint32_t base, int row, int kc) {
    return base + row * 128 + ((kc ^ (row & 7)) << 4);
}
__device__ __forceinline__ int load_idx(const void* ei, size_t pos) {
    if (d_is64) return (int)((const long long*)ei)[pos];
    return ((const int*)ei)[pos];
}
// fma of 8 fp16 values (packed in uint4) into 8 fp32 accumulators
__device__ __forceinline__ void fma8(float* acc, uint4 v, float w) {
    __half2* h = (__half2*)&v;
#pragma unroll
    for (int i = 0; i < 4; i++) {
        float2 f = __half22float2(h[i]);
        acc[2 * i]     += w * f.x;
        acc[2 * i + 1] += w * f.y;
    }
}

// ---------------- setup kernels ----------------
__global__ void k_zero(const unsigned long long* __restrict__ ei) {
    int i = blockIdx.x * 256 + threadIdx.x;
    if (i < NN) d_deg[i] = 0;
    if (i == 0) {
        int is64 = 1;
        for (int j = 0; j < 128; j++)
            if (ei[j] >= (1ull << 32)) { is64 = 0; break; }
        d_is64 = is64;
    }
}
__global__ void k_count(const void* __restrict__ ei) {
    int e = blockIdx.x * 256 + threadIdx.x;
    if (e < EE) atomicAdd(&d_deg[load_idx(ei, (size_t)EE + e)], 1);
}
// ---- 3-phase parallel scan (edge-only counts; self-loop via +1 in dinv)
__global__ __launch_bounds__(512) void k_scan1() {
    __shared__ int sw[16];
    int b = blockIdx.x, tid = threadIdx.x;
    int i = b * 512 + tid;
    int lane = tid & 31, wid = tid >> 5;
    int deg = (i < NN) ? d_deg[i] : 0;
    if (i < NN) d_dinv[i] = rsqrtf((float)(deg + 1));
    int x = deg;
#pragma unroll
    for (int d = 1; d < 32; d <<= 1) {
        int t = __shfl_up_sync(0xffffffffu, x, d);
        if (lane >= d) x += t;
    }
    if (lane == 31) sw[wid] = x;
    __syncthreads();
    if (wid == 0 && lane < 16) {
        int y = sw[lane];
#pragma unroll
        for (int d = 1; d < 16; d <<= 1) {
            int t = __shfl_up_sync(0xffffu, y, d);
            if (lane >= d) y += t;
        }
        sw[lane] = y;
    }
    __syncthreads();
    int incl = x + ((wid > 0) ? sw[wid - 1] : 0);
    if (i < NN) d_rowptr[i + 1] = incl;
    if (tid == 511) d_bsum[b] = incl;
}
__global__ __launch_bounds__(128) void k_scan2() {
    __shared__ int sw[4];
    int tid = threadIdx.x, lane = tid & 31, wid = tid >> 5;
    int v = (tid < NB_S) ? d_bsum[tid] : 0;
    int x = v;
#pragma unroll
    for (int d = 1; d < 32; d <<= 1) {
        int t = __shfl_up_sync(0xffffffffu, x, d);
        if (lane >= d) x += t;
    }
    if (lane == 31) sw[wid] = x;
    __syncthreads();
    if (wid == 0 && lane < 4) {
        int y = sw[lane];
#pragma unroll
        for (int d = 1; d < 4; d <<= 1) {
            int t = __shfl_up_sync(0xfu, y, d);
            if (lane >= d) y += t;
        }
        sw[lane] = y;
    }
    __syncthreads();
    int incl = x + ((wid > 0) ? sw[wid - 1] : 0);
    if (tid < NB_S) d_boff[tid] = incl - v;  // exclusive
}
__global__ __launch_bounds__(512) void k_scan3() {
    int i = blockIdx.x * 512 + threadIdx.x;
    if (i < NN) {
        int r = d_rowptr[i + 1] + d_boff[i >> 9];
        d_rowptr[i + 1] = r;
        d_cursor[i]     = r - d_deg[i];
    }
    if (i == 0) d_rowptr[0] = 0;
}
__global__ void k_fill(const void* __restrict__ ei) {
    int e = blockIdx.x * 256 + threadIdx.x;
    if (e < EE) {
        int s = load_idx(ei, (size_t)e);
        int d = load_idx(ei, (size_t)EE + e);
        int pos = atomicAdd(&d_cursor[d], 1);
        d_csr[pos] = make_int2(s, __float_as_int(d_dinv[s] * d_dinv[d]));
    }
}

// pack + transpose weights to fp16
__global__ void k_pack2(const float* __restrict__ W1,
                        const float* __restrict__ Wmu, const float* __restrict__ Wls,
                        const float* __restrict__ bmu, const float* __restrict__ bls) {
    int idx = blockIdx.x * 256 + threadIdx.x;
    if (idx < 65536) {
        int n = idx >> 8, k = idx & 255;
        d_W1Tf16[idx] = __float2half_rn(W1[k * 256 + n]);
        float bc = (n < OUTC) ? Wmu[k * OUTC + n] : Wls[k * OUTC + (n - OUTC)];
        d_BcTf16[idx] = __float2half_rn(bc);
    }
    if (idx < 256) d_bcat[idx] = (idx < OUTC) ? bmu[idx] : bls[idx - OUTC];
}

// ---------------- aggregation (fp16 gather via CSR, fp32 accumulate) ----------
// BUF=0: d_h0f16 -> d_hf16 (relu+bias). BUF=1: d_hf16 -> d_gf16.
// block (32,8): 8 nodes/block, 32 lanes x uint4(8 halves) cover 256 features.
template <int BUF>
__global__ __launch_bounds__(256) void k_agg(const float* __restrict__ bias) {
    int node = blockIdx.x * 8 + threadIdx.y;
    if (node >= NN) return;
    int lane = threadIdx.x;  // handles features [lane*8, lane*8+8)
    const uint4* sf = (BUF == 0) ? (const uint4*)d_h0f16 : (const uint4*)d_hf16;

    float di = d_dinv[node];
    float w0 = di * di;
    float acc[8];
    {
        uint4 v = sf[(size_t)node * 32 + lane];
        __half2* h = (__half2*)&v;
#pragma unroll
        for (int i = 0; i < 4; i++) {
            float2 f = __half22float2(h[i]);
            acc[2 * i]     = w0 * f.x;
            acc[2 * i + 1] = w0 * f.y;
        }
    }

    int beg = d_rowptr[node], end = d_rowptr[node + 1];
    int e = beg;
    for (; e + 4 <= end; e += 4) {
        int2 c0 = d_csr[e];
        int2 c1 = d_csr[e + 1];
        int2 c2 = d_csr[e + 2];
        int2 c3 = d_csr[e + 3];
        uint4 v0 = sf[(size_t)c0.x * 32 + lane];
        uint4 v1 = sf[(size_t)c1.x * 32 + lane];
        uint4 v2 = sf[(size_t)c2.x * 32 + lane];
        uint4 v3 = sf[(size_t)c3.x * 32 + lane];
        fma8(acc, v0, __int_as_float(c0.y));
        fma8(acc, v1, __int_as_float(c1.y));
        fma8(acc, v2, __int_as_float(c2.y));
        fma8(acc, v3, __int_as_float(c3.y));
    }
    for (; e < end; e++) {
        int2 c = d_csr[e];
        uint4 v = sf[(size_t)c.x * 32 + lane];
        fma8(acc, v, __int_as_float(c.y));
    }

    uint4 outv;
    __half2* oh = (__half2*)&outv;
    if (BUF == 0) {
        const float4* b4 = (const float4*)bias;
        float4 ba = b4[lane * 2];
        float4 bb = b4[lane * 2 + 1];
        float bv[8] = {ba.x, ba.y, ba.z, ba.w, bb.x, bb.y, bb.z, bb.w};
#pragma unroll
        for (int i = 0; i < 4; i++) {
            float fx = fmaxf(acc[2 * i]     + bv[2 * i],     0.f);
            float fy = fmaxf(acc[2 * i + 1] + bv[2 * i + 1], 0.f);
            oh[i] = __floats2half2_rn(fx, fy);
        }
        ((uint4*)d_hf16)[(size_t)node * 32 + lane] = outv;
    } else {
#pragma unroll
        for (int i = 0; i < 4; i++)
            oh[i] = __floats2half2_rn(acc[2 * i], acc[2 * i + 1]);
        ((uint4*)d_gf16)[(size_t)node * 32 + lane] = outv;
    }
}

// ---------------- mma.sync fp16 GEMM (single-term) ----------------
// MODE 0: h0f16 = x @ W1^T (x fp32 converted in-loader), grid (2, 391).
// MODE 1: [mu|ls] = g @ Bc^T + bias -> out (g fp16), grid (2, 391).
#define TILE_B 16384
#define GSMEM  (2 * TILE_B)

// copy 128 rows x 64 fp16 chunk into swizzled smem tile
__device__ __forceinline__ void load_tile64_h(char* tile, const __half* __restrict__ src,
                                              int row0, int nvalid, int col0) {
    int t = threadIdx.x;
    int r = t >> 1;
    int hb = (t & 1) * 64;
    const char* srow = (const char*)(src + (size_t)(row0 + r) * 256 + col0);
    bool valid = r < nvalid;
#pragma unroll
    for (int i = 0; i < 4; i++) {
        int b = hb + i * 16;
        uint4 v = valid ? *(const uint4*)(srow + b) : make_uint4(0u, 0u, 0u, 0u);
        uint32_t off = (uint32_t)(r * 128 + b);
        off ^= ((off >> 3) & 0x70);
        *(uint4*)(tile + off) = v;
    }
}

// load 128 rows x 64 fp32 chunk, convert to fp16 swizzled tile
__device__ __forceinline__ void load_tile64_cvt(char* tile, const float* __restrict__ src,
                                                int row0, int nvalid, int col0) {
    int t = threadIdx.x;
    int r = t >> 1;
    int hf = (t & 1) * 32;
    const float* srow = src + (size_t)(row0 + r) * 256 + col0 + hf;
    bool valid = r < nvalid;
#pragma unroll
    for (int i = 0; i < 4; i++) {
        float4 f0 = valid ? *(const float4*)(srow + i * 8)     : make_float4(0.f, 0.f, 0.f, 0.f);
        float4 f1 = valid ? *(const float4*)(srow + i * 8 + 4) : make_float4(0.f, 0.f, 0.f, 0.f);
        uint4 hv;
        __half2* h = (__half2*)&hv;
        h[0] = __floats2half2_rn(f0.x, f0.y);
        h[1] = __floats2half2_rn(f0.z, f0.w);
        h[2] = __floats2half2_rn(f1.x, f1.y);
        h[3] = __floats2half2_rn(f1.z, f1.w);
        uint32_t off = (uint32_t)(r * 128 + hf * 2 + i * 16);
        off ^= ((off >> 3) & 0x70);
        *(uint4*)(tile + off) = hv;
    }
}

template <int MODE>
__global__ __launch_bounds__(256) void k_gemm_mma(const float* __restrict__ Ax,
                                                  float* __restrict__ Cp) {
    extern __shared__ char smem[];
    char* sA = smem;
    char* sB = smem + TILE_B;
    uint32_t bA = smem_u32(sA), bB = bA + TILE_B;

    int tid = threadIdx.x, wid = tid >> 5, lane = tid & 31;
    int wm = wid >> 1, wn = wid & 1;
    int bn = blockIdx.x * 128;
    int bm = blockIdx.y * 128;

    const __half* B = (MODE == 0) ? d_W1Tf16 : d_BcTf16;

    int navalid = NN - bm; if (navalid > 128) navalid = 128;

    float acc[2][8][4];
#pragma unroll
    for (int i = 0; i < 2; i++)
#pragma unroll
        for (int j = 0; j < 8; j++)
#pragma unroll
            for (int q = 0; q < 4; q++) acc[i][j][q] = 0.f;

    int a_row_off = ((lane >> 3) & 1) * 8 + (lane & 7);
    int a_kc_off  = (lane >> 4);
    int b_row_off = (lane >> 4) * 8 + (lane & 7);
    int b_kc_off  = ((lane >> 3) & 1);

    for (int c = 0; c < 4; c++) {
        if (c > 0) __syncthreads();
        if (MODE == 0) {
            load_tile64_cvt(sA, Ax, bm, navalid, c * 64);
        } else {
            load_tile64_h(sA, d_gf16, bm, navalid, c * 64);
        }
        load_tile64_h(sB, B, bn, 128, c * 64);
        __syncthreads();

#pragma unroll
        for (int ks = 0; ks < 4; ks++) {
            int kc0 = ks * 2;
            uint32_t a[2][4];
#pragma unroll
            for (int mi = 0; mi < 2; mi++) {
                int row = wm * 32 + mi * 16 + a_row_off;
                int kc  = kc0 + a_kc_off;
                ldmat_x4(a[mi][0], a[mi][1], a[mi][2], a[mi][3], sw_addr(bA, row, kc));
            }
#pragma unroll
            for (int ng = 0; ng < 4; ng++) {
                int nrow = wn * 64 + ng * 16 + b_row_off;
                int kc   = kc0 + b_kc_off;
                uint32_t b[4];
                ldmat_x4(b[0], b[1], b[2], b[3], sw_addr(bB, nrow, kc));
#pragma unroll
                for (int mi = 0; mi < 2; mi++) {
                    mma_f16(acc[mi][ng * 2],     a[mi], b[0], b[1]);
                    mma_f16(acc[mi][ng * 2 + 1], a[mi], b[2], b[3]);
                }
            }
        }
    }

#pragma unroll
    for (int mi = 0; mi < 2; mi++) {
        int r0 = bm + wm * 32 + mi * 16 + (lane >> 2);
#pragma unroll
        for (int ni = 0; ni < 8; ni++) {
            int col = wn * 64 + ni * 8 + (lane & 3) * 2;
            float* a = acc[mi][ni];
            if (MODE == 0) {
                if (r0 < NN)
                    *(__half2*)&d_h0f16[(size_t)r0 * 256 + bn + col] =
                        __floats2half2_rn(a[0], a[1]);
                if (r0 + 8 < NN)
                    *(__half2*)&d_h0f16[(size_t)(r0 + 8) * 256 + bn + col] =
                        __floats2half2_rn(a[2], a[3]);
            } else {
                float bx = d_bcat[bn + col], by = d_bcat[bn + col + 1];
                size_t half_off = (bn == 0) ? 0 : (size_t)NN * OUTC;
                if (r0 < NN)
                    *(float2*)&Cp[half_off + (size_t)r0 * OUTC + col] =
                        make_float2(a[0] + bx, a[1] + by);
                if (r0 + 8 < NN)
                    *(float2*)&Cp[half_off + (size_t)(r0 + 8) * OUTC + col] =
                        make_float2(a[2] + bx, a[3] + by);
            }
        }
    }
}

// ---------------- launch ----------------
extern "C" void kernel_launch(void* const* d_in, const int* in_sizes, int n_in,
                              void* d_out, int out_size) {
    const float* x   = (const float*)d_in[0];
    const void*  ei  = d_in[1];
    const float* W1  = (const float*)d_in[2];
    const float* b1  = (const float*)d_in[3];
    const float* Wmu = (const float*)d_in[4];
    const float* bmu = (const float*)d_in[5];
    const float* Wls = (const float*)d_in[6];
    const float* bls = (const float*)d_in[7];
    float* out = (float*)d_out;

    cudaFuncSetAttribute(k_gemm_mma<0>, cudaFuncAttributeMaxDynamicSharedMemorySize, GSMEM);
    cudaFuncSetAttribute(k_gemm_mma<1>, cudaFuncAttributeMaxDynamicSharedMemorySize, GSMEM);

    dim3 ggrid(2, (NN + 127) / 128);
    dim3 agrid((NN + 7) / 8);
    dim3 ablk(32, 8);

    cudaStream_t s1;
    cudaStreamCreateWithFlags(&s1, cudaStreamNonBlocking);
    cudaEvent_t e0, eG0;
    cudaEventCreateWithFlags(&e0,  cudaEventDisableTiming);
    cudaEventCreateWithFlags(&eG0, cudaEventDisableTiming);

    cudaEventRecord(e0, 0);
    cudaStreamWaitEvent(s1, e0, 0);

    // branch B (s1): pack weights, then GEMM0 (x @ W1 -> d_h0f16)
    k_pack2<<<(65536 + 255) / 256, 256, 0, s1>>>(W1, Wmu, Wls, bmu, bls);
    k_gemm_mma<0><<<ggrid, 256, GSMEM, s1>>>(x, nullptr);
    cudaEventRecord(eG0, s1);

    // branch A (stream 0): CSR build
    k_zero<<<(NN + 255) / 256, 256>>>((const unsigned long long*)ei);
    k_count<<<(EE + 255) / 256, 256>>>(ei);
    k_scan1<<<NB_S, 512>>>();
    k_scan2<<<1, 128>>>();
    k_scan3<<<NB_S, 512>>>();
    k_fill<<<(EE + 255) / 256, 256>>>(ei);

    // join: agg0 needs d_h0f16 + CSR
    cudaStreamWaitEvent(0, eG0, 0);
    k_agg<0><<<agrid, ablk>>>(b1);
    k_agg<1><<<agrid, ablk>>>(nullptr);
    k_gemm_mma<1><<<ggrid, 256, GSMEM>>>(nullptr, out);
}

// round 15
// speedup vs baseline: 2.2430x; 1.0422x over previous
#include <cuda_runtime.h>
#include <cuda_bf16.h>
#include <cuda_fp16.h>
#include <cstdint>

#define NN   50000
#define EE   800000
#define HIDC 256
#define OUTC 128
#define NB_S 98   // ceil(NN/512)

// ---------------- scratch (static device globals; no allocation) ----------------
__device__ int   d_is64;
__device__ int   d_deg[NN];
__device__ float d_dinv[NN];
__device__ int   d_rowptr[NN + 1];
__device__ int   d_cursor[NN];
__device__ int   d_bsum[NB_S];
__device__ int   d_boff[NB_S];
__device__ int2  d_csr[EE];                    // (src, w as float bits)
__device__ __half d_h0f16[(size_t)NN * HIDC];  // x @ W1 (fp16)
__device__ __half d_hf16 [(size_t)NN * HIDC];  // relu(Agg(h0) + b1) (fp16)
__device__ __half d_gf16 [(size_t)NN * HIDC];  // Agg(h) (fp16)
__device__ __half d_W1Tf16[HIDC * HIDC];       // W1^T  [n][k] fp16
__device__ __half d_BcTf16[HIDC * HIDC];       // [Wmu|Wls]^T [n][k] fp16
__device__ float d_bcat[256];                  // [b_mu | b_ls]

// ---------------- helpers ----------------
__device__ __forceinline__ uint32_t smem_u32(const void* p) {
    uint32_t a;
    asm("{ .reg .u64 t; cvta.to.shared.u64 t, %1; cvt.u32.u64 %0, t; }" : "=r"(a) : "l"(p));
    return a;
}
__device__ __forceinline__ void ldmat_x4(uint32_t& r0, uint32_t& r1, uint32_t& r2,
                                         uint32_t& r3, uint32_t addr) {
    asm volatile("ldmatrix.sync.aligned.m8n8.x4.shared.b16 {%0,%1,%2,%3}, [%4];"
                 : "=r"(r0), "=r"(r1), "=r"(r2), "=r"(r3) : "r"(addr));
}
__device__ __forceinline__ void mma_f16(float* c, const uint32_t* a,
                                        uint32_t b0, uint32_t b1) {
    asm volatile("mma.sync.aligned.m16n8k16.row.col.f32.f16.f16.f32 "
                 "{%0,%1,%2,%3}, {%4,%5,%6,%7}, {%8,%9}, {%0,%1,%2,%3};"
                 : "+f"(c[0]), "+f"(c[1]), "+f"(c[2]), "+f"(c[3])
                 : "r"(a[0]), "r"(a[1]), "r"(a[2]), "r"(a[3]), "r"(b0), "r"(b1));
}
__device__ __forceinline__ uint32_t sw_addr(uint32_t base, int row, int kc) {
    return base + row * 128 + ((kc ^ (row & 7)) << 4);
}
__device__ __forceinline__ int load_idx(const void* ei, size_t pos) {
    if (d_is64) return (int)((const long long*)ei)[pos];
    return ((const int*)ei)[pos];
}
__device__ __forceinline__ void fma8(float* acc, uint4 v, float w) {
    __half2* h = (__half2*)&v;
#pragma unroll
    for (int i = 0; i < 4; i++) {
        float2 f = __half22float2(h[i]);
        acc[2 * i]     += w * f.x;
        acc[2 * i + 1] += w * f.y;
    }
}

// ---------------- setup kernels ----------------
__global__ void k_detect(const unsigned long long* __restrict__ ei) {
    if (threadIdx.x == 0) {
        int is64 = 1;
        for (int j = 0; j < 128; j++)
            if (ei[j] >= (1ull << 32)) { is64 = 0; break; }
        d_is64 = is64;
    }
}
// 4 edges per thread (EE % 4 == 0)
__global__ void k_count(const void* __restrict__ ei) {
    int base = (blockIdx.x * 256 + threadIdx.x) * 4;
    if (base < EE) {
#pragma unroll
        for (int j = 0; j < 4; j++)
            atomicAdd(&d_deg[load_idx(ei, (size_t)EE + base + j)], 1);
    }
}
// ---- 3-phase parallel scan (edge-only counts; self-loop via +1 in dinv)
__global__ __launch_bounds__(512) void k_scan1() {
    __shared__ int sw[16];
    int b = blockIdx.x, tid = threadIdx.x;
    int i = b * 512 + tid;
    int lane = tid & 31, wid = tid >> 5;
    int deg = (i < NN) ? d_deg[i] : 0;
    if (i < NN) d_dinv[i] = rsqrtf((float)(deg + 1));
    int x = deg;
#pragma unroll
    for (int d = 1; d < 32; d <<= 1) {
        int t = __shfl_up_sync(0xffffffffu, x, d);
        if (lane >= d) x += t;
    }
    if (lane == 31) sw[wid] = x;
    __syncthreads();
    if (wid == 0 && lane < 16) {
        int y = sw[lane];
#pragma unroll
        for (int d = 1; d < 16; d <<= 1) {
            int t = __shfl_up_sync(0xffffu, y, d);
            if (lane >= d) y += t;
        }
        sw[lane] = y;
    }
    __syncthreads();
    int incl = x + ((wid > 0) ? sw[wid - 1] : 0);
    if (i < NN) d_rowptr[i + 1] = incl;
    if (tid == 511) d_bsum[b] = incl;
}
__global__ __launch_bounds__(128) void k_scan2() {
    __shared__ int sw[4];
    int tid = threadIdx.x, lane = tid & 31, wid = tid >> 5;
    int v = (tid < NB_S) ? d_bsum[tid] : 0;
    int x = v;
#pragma unroll
    for (int d = 1; d < 32; d <<= 1) {
        int t = __shfl_up_sync(0xffffffffu, x, d);
        if (lane >= d) x += t;
    }
    if (lane == 31) sw[wid] = x;
    __syncthreads();
    if (wid == 0 && lane < 4) {
        int y = sw[lane];
#pragma unroll
        for (int d = 1; d < 4; d <<= 1) {
            int t = __shfl_up_sync(0xfu, y, d);
            if (lane >= d) y += t;
        }
        sw[lane] = y;
    }
    __syncthreads();
    int incl = x + ((wid > 0) ? sw[wid - 1] : 0);
    if (tid < NB_S) d_boff[tid] = incl - v;  // exclusive
}
__global__ __launch_bounds__(512) void k_scan3() {
    int i = blockIdx.x * 512 + threadIdx.x;
    if (i < NN) {
        int r = d_rowptr[i + 1] + d_boff[i >> 9];
        d_rowptr[i + 1] = r;
        d_cursor[i]     = r - d_deg[i];
    }
    if (i == 0) d_rowptr[0] = 0;
}
// 4 edges per thread
__global__ void k_fill(const void* __restrict__ ei) {
    int base = (blockIdx.x * 256 + threadIdx.x) * 4;
    if (base < EE) {
#pragma unroll
        for (int j = 0; j < 4; j++) {
            int e = base + j;
            int s = load_idx(ei, (size_t)e);
            int d = load_idx(ei, (size_t)EE + e);
            int pos = atomicAdd(&d_cursor[d], 1);
            d_csr[pos] = make_int2(s, __float_as_int(d_dinv[s] * d_dinv[d]));
        }
    }
}

// pack + transpose weights to fp16
__global__ void k_pack2(const float* __restrict__ W1,
                        const float* __restrict__ Wmu, const float* __restrict__ Wls,
                        const float* __restrict__ bmu, const float* __restrict__ bls) {
    int idx = blockIdx.x * 256 + threadIdx.x;
    if (idx < 65536) {
        int n = idx >> 8, k = idx & 255;
        d_W1Tf16[idx] = __float2half_rn(W1[k * 256 + n]);
        float bc = (n < OUTC) ? Wmu[k * OUTC + n] : Wls[k * OUTC + (n - OUTC)];
        d_BcTf16[idx] = __float2half_rn(bc);
    }
    if (idx < 256) d_bcat[idx] = (idx < OUTC) ? bmu[idx] : bls[idx - OUTC];
}

// ---------------- aggregation (fp16 gather via CSR, fp32 accumulate) ----------
// BUF=0: d_h0f16 -> d_hf16 (relu+bias). BUF=1: d_hf16 -> d_gf16.
template <int BUF>
__global__ __launch_bounds__(256) void k_agg(const float* __restrict__ bias) {
    int node = blockIdx.x * 8 + threadIdx.y;
    if (node >= NN) return;
    int lane = threadIdx.x;  // handles features [lane*8, lane*8+8)
    const uint4* sf = (BUF == 0) ? (const uint4*)d_h0f16 : (const uint4*)d_hf16;

    float di = d_dinv[node];
    float w0 = di * di;
    float acc[8];
    {
        uint4 v = sf[(size_t)node * 32 + lane];
        __half2* h = (__half2*)&v;
#pragma unroll
        for (int i = 0; i < 4; i++) {
            float2 f = __half22float2(h[i]);
            acc[2 * i]     = w0 * f.x;
            acc[2 * i + 1] = w0 * f.y;
        }
    }

    int beg = d_rowptr[node], end = d_rowptr[node + 1];
    int e = beg;
    for (; e + 4 <= end; e += 4) {
        int2 c0 = d_csr[e];
        int2 c1 = d_csr[e + 1];
        int2 c2 = d_csr[e + 2];
        int2 c3 = d_csr[e + 3];
        uint4 v0 = sf[(size_t)c0.x * 32 + lane];
        uint4 v1 = sf[(size_t)c1.x * 32 + lane];
        uint4 v2 = sf[(size_t)c2.x * 32 + lane];
        uint4 v3 = sf[(size_t)c3.x * 32 + lane];
        fma8(acc, v0, __int_as_float(c0.y));
        fma8(acc, v1, __int_as_float(c1.y));
        fma8(acc, v2, __int_as_float(c2.y));
        fma8(acc, v3, __int_as_float(c3.y));
    }
    for (; e < end; e++) {
        int2 c = d_csr[e];
        uint4 v = sf[(size_t)c.x * 32 + lane];
        fma8(acc, v, __int_as_float(c.y));
    }

    uint4 outv;
    __half2* oh = (__half2*)&outv;
    if (BUF == 0) {
        const float4* b4 = (const float4*)bias;
        float4 ba = b4[lane * 2];
        float4 bb = b4[lane * 2 + 1];
        float bv[8] = {ba.x, ba.y, ba.z, ba.w, bb.x, bb.y, bb.z, bb.w};
#pragma unroll
        for (int i = 0; i < 4; i++) {
            float fx = fmaxf(acc[2 * i]     + bv[2 * i],     0.f);
            float fy = fmaxf(acc[2 * i + 1] + bv[2 * i + 1], 0.f);
            oh[i] = __floats2half2_rn(fx, fy);
        }
        ((uint4*)d_hf16)[(size_t)node * 32 + lane] = outv;
    } else {
#pragma unroll
        for (int i = 0; i < 4; i++)
            oh[i] = __floats2half2_rn(acc[2 * i], acc[2 * i + 1]);
        ((uint4*)d_gf16)[(size_t)node * 32 + lane] = outv;
    }
}

// ---------------- mma.sync fp16 GEMM, 512 threads, full N=256 per block -------
// MODE 0: h0f16 = x @ W1^T (x fp32 converted in-loader), grid (391).
// MODE 1: [mu|ls] = g @ Bc^T + bias -> out, grid (391).
// 16 warps: wm = wid&3 (4 x 32 rows), wn = wid>>2 (4 x 64 cols). A read ONCE.
#define TILE_A 16384   // 128 rows x 128B (64 fp16)
#define TILE_BB 32768  // 256 rows x 128B
#define GSMEM  (TILE_A + TILE_BB)

// A fp16: 128 rows x 64 halves; 512 threads: 4 threads/row x 32B
__device__ __forceinline__ void load_tileA_h(char* tile, const __half* __restrict__ src,
                                             int row0, int nvalid, int col0) {
    int t = threadIdx.x;
    int r = t >> 2;
    int qb = (t & 3) * 32;
    const char* srow = (const char*)(src + (size_t)(row0 + r) * 256 + col0);
    bool valid = r < nvalid;
#pragma unroll
    for (int i = 0; i < 2; i++) {
        int b = qb + i * 16;
        uint4 v = valid ? *(const uint4*)(srow + b) : make_uint4(0u, 0u, 0u, 0u);
        uint32_t off = (uint32_t)(r * 128 + b);
        off ^= ((off >> 3) & 0x70);
        *(uint4*)(tile + off) = v;
    }
}
// A fp32->fp16: 128 rows x 64 floats; 512 threads: 4 threads/row x 16 floats
__device__ __forceinline__ void load_tileA_cvt(char* tile, const float* __restrict__ src,
                                               int row0, int nvalid, int col0) {
    int t = threadIdx.x;
    int r = t >> 2;
    int qf = (t & 3) * 16;
    const float* srow = src + (size_t)(row0 + r) * 256 + col0 + qf;
    bool valid = r < nvalid;
#pragma unroll
    for (int i = 0; i < 2; i++) {
        float4 f0 = valid ? *(const float4*)(srow + i * 8)     : make_float4(0.f, 0.f, 0.f, 0.f);
        float4 f1 = valid ? *(const float4*)(srow + i * 8 + 4) : make_float4(0.f, 0.f, 0.f, 0.f);
        uint4 hv;
        __half2* h = (__half2*)&hv;
        h[0] = __floats2half2_rn(f0.x, f0.y);
        h[1] = __floats2half2_rn(f0.z, f0.w);
        h[2] = __floats2half2_rn(f1.x, f1.y);
        h[3] = __floats2half2_rn(f1.z, f1.w);
        uint32_t off = (uint32_t)(r * 128 + qf * 2 + i * 16);
        off ^= ((off >> 3) & 0x70);
        *(uint4*)(tile + off) = hv;
    }
}
// B fp16: 256 rows x 64 halves; 512 threads: 2 threads/row x 64B
__device__ __forceinline__ void load_tileB_h(char* tile, const __half* __restrict__ src,
                                             int col0) {
    int t = threadIdx.x;
    int r = t >> 1;
    int hb = (t & 1) * 64;
    const char* srow = (const char*)(src + (size_t)r * 256 + col0);
#pragma unroll
    for (int i = 0; i < 4; i++) {
        int b = hb + i * 16;
        uint4 v = *(const uint4*)(srow + b);
        uint32_t off = (uint32_t)(r * 128 + b);
        off ^= ((off >> 3) & 0x70);
        *(uint4*)(tile + off) = v;
    }
}

template <int MODE>
__global__ __launch_bounds__(512) void k_gemm_mma(const float* __restrict__ Ax,
                                                  float* __restrict__ Cp) {
    extern __shared__ char smem[];
    char* sA = smem;
    char* sB = smem + TILE_A;
    uint32_t bA = smem_u32(sA), bB = bA + TILE_A;

    int tid = threadIdx.x, wid = tid >> 5, lane = tid & 31;
    int wm = wid & 3, wn = wid >> 2;
    int bm = blockIdx.x * 128;

    const __half* B = (MODE == 0) ? d_W1Tf16 : d_BcTf16;

    int navalid = NN - bm; if (navalid > 128) navalid = 128;

    float acc[2][8][4];
#pragma unroll
    for (int i = 0; i < 2; i++)
#pragma unroll
        for (int j = 0; j < 8; j++)
#pragma unroll
            for (int q = 0; q < 4; q++) acc[i][j][q] = 0.f;

    int a_row_off = ((lane >> 3) & 1) * 8 + (lane & 7);
    int a_kc_off  = (lane >> 4);
    int b_row_off = (lane >> 4) * 8 + (lane & 7);
    int b_kc_off  = ((lane >> 3) & 1);

    for (int c = 0; c < 4; c++) {
        if (c > 0) __syncthreads();
        if (MODE == 0) load_tileA_cvt(sA, Ax, bm, navalid, c * 64);
        else           load_tileA_h(sA, d_gf16, bm, navalid, c * 64);
        load_tileB_h(sB, B, c * 64);
        __syncthreads();

#pragma unroll
        for (int ks = 0; ks < 4; ks++) {
            int kc0 = ks * 2;
            uint32_t a[2][4];
#pragma unroll
            for (int mi = 0; mi < 2; mi++) {
                int row = wm * 32 + mi * 16 + a_row_off;
                ldmat_x4(a[mi][0], a[mi][1], a[mi][2], a[mi][3],
                         sw_addr(bA, row, kc0 + a_kc_off));
            }
#pragma unroll
            for (int ng = 0; ng < 4; ng++) {
                int nrow = wn * 64 + ng * 16 + b_row_off;
                uint32_t b[4];
                ldmat_x4(b[0], b[1], b[2], b[3], sw_addr(bB, nrow, kc0 + b_kc_off));
#pragma unroll
                for (int mi = 0; mi < 2; mi++) {
                    mma_f16(acc[mi][ng * 2],     a[mi], b[0], b[1]);
                    mma_f16(acc[mi][ng * 2 + 1], a[mi], b[2], b[3]);
                }
            }
        }
    }

#pragma unroll
    for (int mi = 0; mi < 2; mi++) {
        int r0 = bm + wm * 32 + mi * 16 + (lane >> 2);
#pragma unroll
        for (int ni = 0; ni < 8; ni++) {
            int ng = wn * 64 + ni * 8 + (lane & 3) * 2;  // global col 0..255
            float* a = acc[mi][ni];
            if (MODE == 0) {
                if (r0 < NN)
                    *(__half2*)&d_h0f16[(size_t)r0 * 256 + ng] =
                        __floats2half2_rn(a[0], a[1]);
                if (r0 + 8 < NN)
                    *(__half2*)&d_h0f16[(size_t)(r0 + 8) * 256 + ng] =
                        __floats2half2_rn(a[2], a[3]);
            } else {
                float bx = d_bcat[ng], by = d_bcat[ng + 1];
                size_t half_off = (ng < OUTC) ? 0 : (size_t)NN * OUTC;
                int ocol = ng & (OUTC - 1);
                if (r0 < NN)
                    *(float2*)&Cp[half_off + (size_t)r0 * OUTC + ocol] =
                        make_float2(a[0] + bx, a[1] + by);
                if (r0 + 8 < NN)
                    *(float2*)&Cp[half_off + (size_t)(r0 + 8) * OUTC + ocol] =
                        make_float2(a[2] + bx, a[3] + by);
            }
        }
    }
}

// ---------------- launch ----------------
extern "C" void kernel_launch(void* const* d_in, const int* in_sizes, int n_in,
                              void* d_out, int out_size) {
    const float* x   = (const float*)d_in[0];
    const void*  ei  = d_in[1];
    const float* W1  = (const float*)d_in[2];
    const float* b1  = (const float*)d_in[3];
    const float* Wmu = (const float*)d_in[4];
    const float* bmu = (const float*)d_in[5];
    const float* Wls = (const float*)d_in[6];
    const float* bls = (const float*)d_in[7];
    float* out = (float*)d_out;

    cudaFuncSetAttribute(k_gemm_mma<0>, cudaFuncAttributeMaxDynamicSharedMemorySize, GSMEM);
    cudaFuncSetAttribute(k_gemm_mma<1>, cudaFuncAttributeMaxDynamicSharedMemorySize, GSMEM);

    void* p_deg = nullptr;
    cudaGetSymbolAddress(&p_deg, d_deg);

    dim3 ggrid((NN + 127) / 128);
    dim3 agrid((NN + 7) / 8);
    dim3 ablk(32, 8);

    cudaStream_t s1;
    cudaStreamCreateWithFlags(&s1, cudaStreamNonBlocking);
    cudaEvent_t e0, eG0;
    cudaEventCreateWithFlags(&e0,  cudaEventDisableTiming);
    cudaEventCreateWithFlags(&eG0, cudaEventDisableTiming);

    cudaEventRecord(e0, 0);
    cudaStreamWaitEvent(s1, e0, 0);

    // branch B (s1): pack weights, then GEMM0 (x @ W1 -> d_h0f16)
    k_pack2<<<(65536 + 255) / 256, 256, 0, s1>>>(W1, Wmu, Wls, bmu, bls);
    k_gemm_mma<0><<<ggrid, 512, GSMEM, s1>>>(x, nullptr);
    cudaEventRecord(eG0, s1);

    // branch A (stream 0): CSR build
    cudaMemsetAsync(p_deg, 0, NN * sizeof(int), 0);
    k_detect<<<1, 32>>>((const unsigned long long*)ei);
    k_count<<<(EE / 4 + 255) / 256, 256>>>(ei);
    k_scan1<<<NB_S, 512>>>();
    k_scan2<<<1, 128>>>();
    k_scan3<<<NB_S, 512>>>();
    k_fill<<<(EE / 4 + 255) / 256, 256>>>(ei);

    // join: agg0 needs d_h0f16 + CSR
    cudaStreamWaitEvent(0, eG0, 0);
    k_agg<0><<<agrid, ablk>>>(b1);
    k_agg<1><<<agrid, ablk>>>(nullptr);
    k_gemm_mma<1><<<ggrid, 512, GSMEM>>>(nullptr, out);
}